// round 2
// baseline (speedup 1.0000x reference)
#include <cuda_runtime.h>
#include <cuda_bf16.h>
#include <cstdint>
#include <cstddef>

// ============================================================
// BinaryLinear: out[t,o] = sum_k x[t,k] * sign(w[o,k]) + bias[o]
// x: [8192,4096] f32, w: [4096,4096] f32, bias: [4096] f32
// x -> (hi,lo) bf16 split; sign(w) exact in bf16; 2 bf16 GEMMs
// accumulated in fp32.
// Path A (sm_103a/100a device pass): tcgen05 SS MMA, BM=128 BN=256,
//   double-buffered smem stages + per-stage mbarrier (load/MMA overlap).
// Path B (plain sm_103 pass): cp.async 2-stage + ldmatrix + mma.sync bf16.
// ============================================================

#if defined(__CUDA_ARCH_FEAT_SM103_ALL) || defined(__CUDA_ARCH_FEAT_SM100_ALL) || defined(__CUDA_ARCH_FEAT_SM101_ALL)
#define HAS_TCGEN05 1
#else
#define HAS_TCGEN05 0
#endif

static constexpr int TOKENS = 8192;
static constexpr int NOUT   = 4096;
static constexpr int KIN    = 4096;

static constexpr int BM = 128, BN = 256, BK = 64;
static constexpr int NKC = KIN / BK;   // 64 k-chunks

// idesc kind::f16: dtype F32(bit4), atype BF16(bit7), btype BF16(bit10),
// N/8<<17, M/16<<24  ->  N=256, M=128
static constexpr uint32_t MMA_IDESC =
    0x490u | (uint32_t)((BN / 8) << 17) | (uint32_t)((BM / 16) << 24);

// smem layout: header 1024B, then 2 stages of 64KB
//   stage: Ah 16KB @ +0, Al 16KB @ +16384, B 32KB @ +32768
static constexpr int SM_PTR    = 0;
static constexpr int SM_MBAR0  = 8;
static constexpr int SM_MBAR1  = 16;
static constexpr int STAGE_SZ  = 65536;
static constexpr int SMEM_BYTES = 1024 + 2 * STAGE_SZ;   // 132096

#define SWZ(o) ((o) ^ (((o) >> 3) & 0x70u))

// Scratch (static device globals — no runtime allocation)
__device__ __align__(16) __nv_bfloat16 g_Ahi[(size_t)TOKENS * KIN];
__device__ __align__(16) __nv_bfloat16 g_Alo[(size_t)TOKENS * KIN];
__device__ __align__(16) __nv_bfloat16 g_Bs [(size_t)NOUT   * KIN];

// ---------------- common helpers ----------------
static __device__ __forceinline__ uint32_t smem_u32(const void* p) {
    uint32_t a;
    asm("{ .reg .u64 t; cvta.to.shared.u64 t, %1; cvt.u32.u64 %0, t; }"
        : "=r"(a) : "l"(p));
    return a;
}

// ---------------- tcgen05 helpers (only referenced in guarded path) ------
static __device__ __forceinline__ uint32_t elect_one() {
    uint32_t r;
    asm volatile("{ .reg .pred p; elect.sync _|p, 0xFFFFFFFF; selp.b32 %0, 1, 0, p; }"
                 : "=r"(r));
    return r;
}
static __device__ __forceinline__ void mbar_init(uint32_t mbar, uint32_t count) {
    asm volatile("mbarrier.init.shared.b64 [%0], %1;" :: "r"(mbar), "r"(count) : "memory");
}
static __device__ __forceinline__ void mbar_wait(uint32_t mbar, uint32_t parity) {
    asm volatile(
        "{\n\t"
        ".reg .pred P;\n\t"
        "WL_%=:\n\t"
        "mbarrier.try_wait.parity.acquire.cta.shared::cta.b64 P, [%0], %1, 0x989680;\n\t"
        "@P bra WD_%=;\n\t"
        "bra WL_%=;\n\t"
        "WD_%=:\n\t"
        "}"
        :: "r"(mbar), "r"(parity) : "memory");
}

#if HAS_TCGEN05
static __device__ __forceinline__ void tmem_alloc(uint32_t smem_dst, uint32_t ncols) {
    asm volatile("tcgen05.alloc.cta_group::1.sync.aligned.shared::cta.b32 [%0], %1;"
                 :: "r"(smem_dst), "r"(ncols) : "memory");
}
static __device__ __forceinline__ void tmem_relinquish() {
    asm volatile("tcgen05.relinquish_alloc_permit.cta_group::1.sync.aligned;");
}
static __device__ __forceinline__ void tmem_dealloc(uint32_t tmem, uint32_t ncols) {
    asm volatile("tcgen05.dealloc.cta_group::1.sync.aligned.b32 %0, %1;"
                 :: "r"(tmem), "r"(ncols));
}
static __device__ __forceinline__ void fence_proxy_async_cta() {
    asm volatile("fence.proxy.async.shared::cta;" ::: "memory");
}
static __device__ __forceinline__ void tc_fence_after() {
    asm volatile("tcgen05.fence::after_thread_sync;" ::: "memory");
}
static __device__ __forceinline__ void mma_commit(uint32_t mbar) {
    asm volatile(
        "tcgen05.commit.cta_group::1.mbarrier::arrive::one.shared::cluster.b64 [%0];"
        :: "r"(mbar) : "memory");
}
static __device__ __forceinline__ void mma_f16_ss(uint32_t d_tmem, uint64_t a_desc,
                                                  uint64_t b_desc, uint32_t idesc,
                                                  bool acc) {
    uint32_t en = acc ? 1u : 0u;
    asm volatile(
        "{\n\t"
        ".reg .pred p;\n\t"
        "setp.ne.u32 p, %5, 0;\n\t"
        "tcgen05.mma.cta_group::1.kind::f16 [%0], %1, %2, %3, {%4, %4, %4, %4}, p;\n\t"
        "}"
        :: "r"(d_tmem), "l"(a_desc), "l"(b_desc), "r"(idesc), "r"(0u), "r"(en)
        : "memory");
}
// SW128 smem matrix descriptor: layout=2, version=1, SBO=64, LBO=1
static __device__ __forceinline__ uint64_t make_desc(uint32_t smem_addr) {
    const uint64_t base =
        (uint64_t(2) << 61) | (uint64_t(1) << 46) | (uint64_t(64) << 32) | (uint64_t(1) << 16);
    return base | ((uint64_t)(smem_addr >> 4) & 0x3FFFu);
}
#define LDTM_X32(r, addr)                                                      \
    asm volatile(                                                              \
        "tcgen05.ld.sync.aligned.32x32b.x32.b32 "                              \
        "{%0, %1, %2, %3, %4, %5, %6, %7, "                                    \
        " %8, %9, %10, %11, %12, %13, %14, %15, "                              \
        " %16, %17, %18, %19, %20, %21, %22, %23, "                            \
        " %24, %25, %26, %27, %28, %29, %30, %31}, [%32];"                     \
        : "=r"((r)[0]),  "=r"((r)[1]),  "=r"((r)[2]),  "=r"((r)[3]),           \
          "=r"((r)[4]),  "=r"((r)[5]),  "=r"((r)[6]),  "=r"((r)[7]),           \
          "=r"((r)[8]),  "=r"((r)[9]),  "=r"((r)[10]), "=r"((r)[11]),          \
          "=r"((r)[12]), "=r"((r)[13]), "=r"((r)[14]), "=r"((r)[15]),          \
          "=r"((r)[16]), "=r"((r)[17]), "=r"((r)[18]), "=r"((r)[19]),          \
          "=r"((r)[20]), "=r"((r)[21]), "=r"((r)[22]), "=r"((r)[23]),          \
          "=r"((r)[24]), "=r"((r)[25]), "=r"((r)[26]), "=r"((r)[27]),          \
          "=r"((r)[28]), "=r"((r)[29]), "=r"((r)[30]), "=r"((r)[31])           \
        : "r"(addr))
#define TMEM_WAIT_LD() asm volatile("tcgen05.wait::ld.sync.aligned;" ::: "memory")
#endif  // HAS_TCGEN05

// ---------------- fallback helpers (legal on any sm_80+) ----------------
static __device__ __forceinline__ void cp_async16(uint32_t dst, const void* src) {
    asm volatile("cp.async.cg.shared.global [%0], [%1], 16;"
                 :: "r"(dst), "l"(__cvta_generic_to_global(src)));
}
#define CP_COMMIT() asm volatile("cp.async.commit_group;" ::: "memory")
#define CP_WAIT1()  asm volatile("cp.async.wait_group 1;" ::: "memory")
#define CP_WAIT0()  asm volatile("cp.async.wait_group 0;" ::: "memory")

#define LDMX4(r, addr)                                                         \
    asm volatile("ldmatrix.sync.aligned.m8n8.x4.shared.b16 {%0,%1,%2,%3}, [%4];" \
                 : "=r"((r)[0]), "=r"((r)[1]), "=r"((r)[2]), "=r"((r)[3])      \
                 : "r"(addr))

static __device__ __forceinline__ void mma_bf16(float* c, const uint32_t* a,
                                                const uint32_t* b) {
    asm volatile(
        "mma.sync.aligned.m16n8k16.row.col.f32.bf16.bf16.f32 "
        "{%0,%1,%2,%3}, {%4,%5,%6,%7}, {%8,%9}, {%0,%1,%2,%3};"
        : "+f"(c[0]), "+f"(c[1]), "+f"(c[2]), "+f"(c[3])
        : "r"(a[0]), "r"(a[1]), "r"(a[2]), "r"(a[3]), "r"(b[0]), "r"(b[1]));
}

// ---------------- prep kernels ----------------
__global__ void prep_A_kernel(const float* __restrict__ x) {
    size_t i = ((size_t)blockIdx.x * blockDim.x + threadIdx.x) * 4;
    if (i >= (size_t)TOKENS * KIN) return;
    float4 v = *reinterpret_cast<const float4*>(x + i);
    float vv[4] = {v.x, v.y, v.z, v.w};
    unsigned short h[4], l[4];
#pragma unroll
    for (int j = 0; j < 4; j++) {
        __nv_bfloat16 hb = __float2bfloat16_rn(vv[j]);
        float r = vv[j] - __bfloat162float(hb);
        __nv_bfloat16 lb = __float2bfloat16_rn(r);
        h[j] = __bfloat16_as_ushort(hb);
        l[j] = __bfloat16_as_ushort(lb);
    }
    *reinterpret_cast<ushort4*>(reinterpret_cast<unsigned short*>(g_Ahi) + i) =
        make_ushort4(h[0], h[1], h[2], h[3]);
    *reinterpret_cast<ushort4*>(reinterpret_cast<unsigned short*>(g_Alo) + i) =
        make_ushort4(l[0], l[1], l[2], l[3]);
}

__global__ void prep_B_kernel(const float* __restrict__ w) {
    size_t i = ((size_t)blockIdx.x * blockDim.x + threadIdx.x) * 4;
    if (i >= (size_t)NOUT * KIN) return;
    float4 v = *reinterpret_cast<const float4*>(w + i);
    float vv[4] = {v.x, v.y, v.z, v.w};
    unsigned short s[4];
#pragma unroll
    for (int j = 0; j < 4; j++) {
        float sv = (vv[j] > 0.0f) ? 1.0f : ((vv[j] < 0.0f) ? -1.0f : 0.0f);
        s[j] = __bfloat16_as_ushort(__float2bfloat16_rn(sv));
    }
    *reinterpret_cast<ushort4*>(reinterpret_cast<unsigned short*>(g_Bs) + i) =
        make_ushort4(s[0], s[1], s[2], s[3]);
}

// ---------------- main GEMM kernel ----------------
__global__ __launch_bounds__(256, 1)
void bingemm_kernel(const float* __restrict__ bias, float* __restrict__ out) {
    extern __shared__ char smem[];

#if HAS_TCGEN05
    // ==================== Path A: tcgen05 ====================
    const uint32_t sb = smem_u32(smem);
    const int tid = threadIdx.x;
    const int wid = tid >> 5;
    const int lid = tid & 31;
    const int mtile = blockIdx.y;
    const int ntile = blockIdx.x;

    if (wid == 0) tmem_alloc(sb + SM_PTR, 256);
    if (tid == 0) { mbar_init(sb + SM_MBAR0, 1); mbar_init(sb + SM_MBAR1, 1); }
    __syncthreads();
    uint32_t tmem;
    asm volatile("ld.shared.b32 %0, [%1];" : "=r"(tmem) : "r"(sb + SM_PTR));
    if (wid == 0) tmem_relinquish();

    const __nv_bfloat16* Ah = g_Ahi + (size_t)mtile * BM * KIN;
    const __nv_bfloat16* Al = g_Alo + (size_t)mtile * BM * KIN;
    const __nv_bfloat16* Bs = g_Bs  + (size_t)ntile * BN * KIN;

    for (int kc = 0; kc < NKC; kc++) {
        const int st = kc & 1;
        const uint32_t stb = 1024u + (uint32_t)st * STAGE_SZ;
        // buffer free only after MMA issued 2 iterations ago completed
        if (kc >= 2) mbar_wait(sb + SM_MBAR0 + 8 * st, (uint32_t)(((kc >> 1) - 1) & 1));

        const int koff = kc * BK;
        // Ah / Al: 128 rows x 128B = 1024 x 16B chunks each
#pragma unroll 4
        for (int c = tid; c < 1024; c += 256) {
            int row = c >> 3, p = c & 7;
            uint4 v = *reinterpret_cast<const uint4*>(Ah + (size_t)row * KIN + koff + p * 8);
            uint32_t off = SWZ((uint32_t)((row << 7) | (p << 4)));
            *reinterpret_cast<uint4*>(smem + stb + off) = v;
        }
#pragma unroll 4
        for (int c = tid; c < 1024; c += 256) {
            int row = c >> 3, p = c & 7;
            uint4 v = *reinterpret_cast<const uint4*>(Al + (size_t)row * KIN + koff + p * 8);
            uint32_t off = SWZ((uint32_t)((row << 7) | (p << 4)));
            *reinterpret_cast<uint4*>(smem + stb + 16384 + off) = v;
        }
        // B: 256 rows x 128B = 2048 chunks
#pragma unroll 8
        for (int c = tid; c < 2048; c += 256) {
            int row = c >> 3, p = c & 7;
            uint4 v = *reinterpret_cast<const uint4*>(Bs + (size_t)row * KIN + koff + p * 8);
            uint32_t off = SWZ((uint32_t)((row << 7) | (p << 4)));
            *reinterpret_cast<uint4*>(smem + stb + 32768 + off) = v;
        }
        __syncthreads();

        if (wid == 0) {
            if (elect_one()) {
                fence_proxy_async_cta();
                uint64_t ahd = make_desc(sb + stb);
                uint64_t ald = make_desc(sb + stb + 16384);
                uint64_t bd  = make_desc(sb + stb + 32768);
#pragma unroll
                for (int s = 0; s < 4; s++)
                    mma_f16_ss(tmem, ahd + 2 * s, bd + 2 * s, MMA_IDESC,
                               (kc > 0) || (s > 0));
#pragma unroll
                for (int s = 0; s < 4; s++)
                    mma_f16_ss(tmem, ald + 2 * s, bd + 2 * s, MMA_IDESC, true);
                mma_commit(sb + SM_MBAR0 + 8 * st);
            }
        }
        // no wait here: next iteration uses the other buffer (overlap)
    }

    // drain both stages: each buffer got NKC/2 = 32 commits -> wait parity (32-1)&1 = 1
    mbar_wait(sb + SM_MBAR0, 1);
    mbar_wait(sb + SM_MBAR1, 1);
    __syncthreads();
    tc_fence_after();

    // Epilogue: warps (wid&3) = subpartition rows; wid>>2 selects col half.
    const int sub  = wid & 3;
    const int half = wid >> 2;
    const int m    = sub * 32 + lid;
    float* stage_all = reinterpret_cast<float*>(smem + 1024);
    float* stage     = stage_all + half * (BM * 32);
    const size_t orow0 = (size_t)mtile * BM;
    const int    ncol0 = ntile * BN;

    for (int it = 0; it < 4; it++) {
        uint32_t r[32];
        LDTM_X32(r, tmem + (uint32_t)(half * 128 + it * 32));
        TMEM_WAIT_LD();
#pragma unroll
        for (int c = 0; c < 32; c++)
            stage[m * 32 + (c ^ (m & 31))] = __uint_as_float(r[c]);
        __syncthreads();
#pragma unroll 4
        for (int e = tid; e < 2 * BM * 32; e += 256) {
            int hh  = e >> 12;
            int rem = e & 4095;
            int row = rem >> 5;
            int c   = rem & 31;
            float v = stage_all[hh * (BM * 32) + row * 32 + (c ^ (row & 31))];
            int gc  = ncol0 + hh * 128 + it * 32 + c;
            out[(orow0 + row) * (size_t)NOUT + gc] = v + __ldg(&bias[gc]);
        }
        __syncthreads();
    }

    if (wid == 0) tmem_dealloc(tmem, 256);

#else
    // ==================== Path B: mma.sync bf16 fallback ====================
    const uint32_t sb = smem_u32(smem);
    const int tid  = threadIdx.x;
    const int lane = tid & 31;
    const int wid  = tid >> 5;
    const int warp_m = wid >> 2;   // 0..1
    const int warp_n = wid & 3;    // 0..3
    const int mtile = blockIdx.y;
    const int ntile = blockIdx.x;

    const __nv_bfloat16* Ah = g_Ahi + (size_t)mtile * BM * KIN;
    const __nv_bfloat16* Al = g_Alo + (size_t)mtile * BM * KIN;
    const size_t orow0 = (size_t)mtile * BM;

    // ldmatrix lane addressing (within the stage's swizzled tiles)
    const int a_row = warp_m * 64 + (lane & 15);
    const int a_kb  = (lane >> 4) << 4;
    const int b_row = warp_n * 32 + (((lane >> 4) << 3) | (lane & 7));
    const int b_kb  = ((lane >> 3) & 1) << 4;

    for (int halfn = 0; halfn < 2; halfn++) {
        const __nv_bfloat16* Bs = g_Bs + ((size_t)ntile * BN + halfn * 128) * KIN;

        float acc[4][4][4];
#pragma unroll
        for (int mt = 0; mt < 4; mt++)
#pragma unroll
            for (int nt = 0; nt < 4; nt++)
#pragma unroll
                for (int j = 0; j < 4; j++) acc[mt][nt][j] = 0.0f;

        // prologue: stage 0 (48KB/stage layout inside the 64KB slots)
        {
            const int koff = 0;
            const uint32_t stb = sb + 1024u;
#pragma unroll 4
            for (int c = tid; c < 1024; c += 256) {
                int row = c >> 3, p = c & 7;
                uint32_t off = SWZ((uint32_t)((row << 7) | (p << 4)));
                cp_async16(stb + off,         Ah + (size_t)row * KIN + koff + p * 8);
                cp_async16(stb + 16384 + off, Al + (size_t)row * KIN + koff + p * 8);
                cp_async16(stb + 32768 + off, Bs + (size_t)row * KIN + koff + p * 8);
            }
            CP_COMMIT();
        }

        for (int kc = 0; kc < NKC; kc++) {
            if (kc + 1 < NKC) {
                const int koff = (kc + 1) * BK;
                const uint32_t stb = sb + 1024u + (uint32_t)((kc + 1) & 1) * STAGE_SZ;
#pragma unroll 4
                for (int c = tid; c < 1024; c += 256) {
                    int row = c >> 3, p = c & 7;
                    uint32_t off = SWZ((uint32_t)((row << 7) | (p << 4)));
                    cp_async16(stb + off,         Ah + (size_t)row * KIN + koff + p * 8);
                    cp_async16(stb + 16384 + off, Al + (size_t)row * KIN + koff + p * 8);
                    cp_async16(stb + 32768 + off, Bs + (size_t)row * KIN + koff + p * 8);
                }
                CP_COMMIT();
                CP_WAIT1();
            } else {
                CP_WAIT0();
            }
            __syncthreads();

            const uint32_t stb = sb + 1024u + (uint32_t)(kc & 1) * STAGE_SZ;
#pragma unroll
            for (int ks = 0; ks < 4; ks++) {
                const int kbyte = ks * 32;
                uint32_t bf[4], bf2[4];
                {
                    uint32_t off = SWZ((uint32_t)(b_row * 128 + kbyte + b_kb));
                    LDMX4(bf, stb + 32768 + off);
                    uint32_t off2 = SWZ((uint32_t)((b_row + 16) * 128 + kbyte + b_kb));
                    LDMX4(bf2, stb + 32768 + off2);
                }
#pragma unroll
                for (int mt = 0; mt < 4; mt++) {
                    uint32_t offa = SWZ((uint32_t)((a_row + mt * 16) * 128 + kbyte + a_kb));
                    uint32_t ah[4], al_[4];
                    LDMX4(ah,  stb + offa);
                    LDMX4(al_, stb + 16384 + offa);
                    mma_bf16(acc[mt][0], ah,  &bf[0]);
                    mma_bf16(acc[mt][0], al_, &bf[0]);
                    mma_bf16(acc[mt][1], ah,  &bf[2]);
                    mma_bf16(acc[mt][1], al_, &bf[2]);
                    mma_bf16(acc[mt][2], ah,  &bf2[0]);
                    mma_bf16(acc[mt][2], al_, &bf2[0]);
                    mma_bf16(acc[mt][3], ah,  &bf2[2]);
                    mma_bf16(acc[mt][3], al_, &bf2[2]);
                }
            }
            __syncthreads();
        }

        // epilogue (direct stores, float2)
        const int col0 = ntile * BN + halfn * 128 + warp_n * 32;
#pragma unroll
        for (int mt = 0; mt < 4; mt++) {
#pragma unroll
            for (int nt = 0; nt < 4; nt++) {
                int r0 = warp_m * 64 + mt * 16 + (lane >> 2);
                int c  = col0 + nt * 8 + (lane & 3) * 2;
                float b0 = __ldg(&bias[c]);
                float b1 = __ldg(&bias[c + 1]);
                float2 v0 = make_float2(acc[mt][nt][0] + b0, acc[mt][nt][1] + b1);
                float2 v1 = make_float2(acc[mt][nt][2] + b0, acc[mt][nt][3] + b1);
                *reinterpret_cast<float2*>(&out[(orow0 + r0) * (size_t)NOUT + c])     = v0;
                *reinterpret_cast<float2*>(&out[(orow0 + r0 + 8) * (size_t)NOUT + c]) = v1;
            }
        }
        __syncthreads();  // smem reuse safety before next half's prologue
    }
#endif
}

// ---------------- launch ----------------
extern "C" void kernel_launch(void* const* d_in, const int* in_sizes, int n_in,
                              void* d_out, int out_size) {
    const float* x    = (const float*)d_in[0];
    const float* w    = (const float*)d_in[1];
    const float* bias = (const float*)d_in[2];
    float* out        = (float*)d_out;

    {
        size_t n4 = (size_t)TOKENS * KIN / 4;
        prep_A_kernel<<<(unsigned)((n4 + 255) / 256), 256>>>(x);
    }
    {
        size_t n4 = (size_t)NOUT * KIN / 4;
        prep_B_kernel<<<(unsigned)((n4 + 255) / 256), 256>>>(w);
    }

    cudaFuncSetAttribute(bingemm_kernel,
                         cudaFuncAttributeMaxDynamicSharedMemorySize, SMEM_BYTES);
    dim3 grid(NOUT / BN, TOKENS / BM);
    bingemm_kernel<<<grid, 256, SMEM_BYTES>>>(bias, out);
}

// round 3
// speedup vs baseline: 1.5700x; 1.5700x over previous
#include <cuda_runtime.h>
#include <cuda_fp16.h>
#include <cstdint>
#include <cstddef>

// ============================================================
// BinaryLinear: out[t,o] = sum_k x[t,k] * sign(w[o,k]) + bias[o]
// x: [8192,4096] f32, w: [4096,4096] f32, bias: [4096] f32
// R3: single fp16 term (rel_err ~3e-4 < 1e-3), sign(w) exact fp16.
// tcgen05 cg1 SS MMA, BM=256 (2x M=128 dispatches) x BN=256, BK=64,
// 3-stage smem pipeline with per-stage mbarrier commit/wait.
// ============================================================

#if defined(__CUDA_ARCH_FEAT_SM103_ALL) || defined(__CUDA_ARCH_FEAT_SM100_ALL) || defined(__CUDA_ARCH_FEAT_SM101_ALL)
#define HAS_TCGEN05 1
#else
#define HAS_TCGEN05 0
#endif

static constexpr int TOKENS = 8192;
static constexpr int NOUT   = 4096;
static constexpr int KIN    = 4096;

static constexpr int BM = 256, BN = 256, BK = 64;
static constexpr int NKC = KIN / BK;   // 64 k-chunks
static constexpr int NSTAGE = 3;

// idesc kind::f16 (fp16 in, fp32 acc): dtype F32(bit4), atype=btype=F16(0),
// N/8<<17, M/16<<24  -> per-dispatch M=128, N=256
static constexpr uint32_t MMA_IDESC =
    0x10u | (uint32_t)((BN / 8) << 17) | (uint32_t)((128 / 16) << 24);

// smem: header 1024B, then 3 stages of 64KB
//   stage: A (256 rows x 128B, halves at +0/+16384), B (256 rows) @ +32768
static constexpr int SM_PTR    = 0;
static constexpr int SM_MBAR   = 8;    // 3 mbarriers @ 8,16,24
static constexpr int STAGE_SZ  = 65536;
static constexpr int SMEM_BYTES = 1024 + NSTAGE * STAGE_SZ;   // 197632

#define SWZ(o) ((o) ^ (((o) >> 3) & 0x70u))

// Scratch (static device globals — no runtime allocation)
__device__ __align__(16) __half g_Ah[(size_t)TOKENS * KIN];   // 64 MB
__device__ __align__(16) __half g_Bs[(size_t)NOUT   * KIN];   // 32 MB

// ---------------- common helpers ----------------
static __device__ __forceinline__ uint32_t smem_u32(const void* p) {
    uint32_t a;
    asm("{ .reg .u64 t; cvta.to.shared.u64 t, %1; cvt.u32.u64 %0, t; }"
        : "=r"(a) : "l"(p));
    return a;
}
static __device__ __forceinline__ uint32_t elect_one() {
    uint32_t r;
    asm volatile("{ .reg .pred p; elect.sync _|p, 0xFFFFFFFF; selp.b32 %0, 1, 0, p; }"
                 : "=r"(r));
    return r;
}
static __device__ __forceinline__ void mbar_init(uint32_t mbar, uint32_t count) {
    asm volatile("mbarrier.init.shared.b64 [%0], %1;" :: "r"(mbar), "r"(count) : "memory");
}
static __device__ __forceinline__ void mbar_wait(uint32_t mbar, uint32_t parity) {
    asm volatile(
        "{\n\t"
        ".reg .pred P;\n\t"
        "WL_%=:\n\t"
        "mbarrier.try_wait.parity.acquire.cta.shared::cta.b64 P, [%0], %1, 0x989680;\n\t"
        "@P bra WD_%=;\n\t"
        "bra WL_%=;\n\t"
        "WD_%=:\n\t"
        "}"
        :: "r"(mbar), "r"(parity) : "memory");
}

#if HAS_TCGEN05
static __device__ __forceinline__ void tmem_alloc(uint32_t smem_dst, uint32_t ncols) {
    asm volatile("tcgen05.alloc.cta_group::1.sync.aligned.shared::cta.b32 [%0], %1;"
                 :: "r"(smem_dst), "r"(ncols) : "memory");
}
static __device__ __forceinline__ void tmem_relinquish() {
    asm volatile("tcgen05.relinquish_alloc_permit.cta_group::1.sync.aligned;");
}
static __device__ __forceinline__ void tmem_dealloc(uint32_t tmem, uint32_t ncols) {
    asm volatile("tcgen05.dealloc.cta_group::1.sync.aligned.b32 %0, %1;"
                 :: "r"(tmem), "r"(ncols));
}
static __device__ __forceinline__ void fence_proxy_async_cta() {
    asm volatile("fence.proxy.async.shared::cta;" ::: "memory");
}
static __device__ __forceinline__ void tc_fence_after() {
    asm volatile("tcgen05.fence::after_thread_sync;" ::: "memory");
}
static __device__ __forceinline__ void mma_commit(uint32_t mbar) {
    asm volatile(
        "tcgen05.commit.cta_group::1.mbarrier::arrive::one.shared::cluster.b64 [%0];"
        :: "r"(mbar) : "memory");
}
static __device__ __forceinline__ void mma_f16_ss(uint32_t d_tmem, uint64_t a_desc,
                                                  uint64_t b_desc, uint32_t idesc,
                                                  bool acc) {
    uint32_t en = acc ? 1u : 0u;
    asm volatile(
        "{\n\t"
        ".reg .pred p;\n\t"
        "setp.ne.u32 p, %5, 0;\n\t"
        "tcgen05.mma.cta_group::1.kind::f16 [%0], %1, %2, %3, {%4, %4, %4, %4}, p;\n\t"
        "}"
        :: "r"(d_tmem), "l"(a_desc), "l"(b_desc), "r"(idesc), "r"(0u), "r"(en)
        : "memory");
}
// SW128 smem matrix descriptor: layout=2, version=1, SBO=64, LBO=1
static __device__ __forceinline__ uint64_t make_desc(uint32_t smem_addr) {
    const uint64_t base =
        (uint64_t(2) << 61) | (uint64_t(1) << 46) | (uint64_t(64) << 32) | (uint64_t(1) << 16);
    return base | ((uint64_t)(smem_addr >> 4) & 0x3FFFu);
}
#define LDTM_X32(r, addr)                                                      \
    asm volatile(                                                              \
        "tcgen05.ld.sync.aligned.32x32b.x32.b32 "                              \
        "{%0, %1, %2, %3, %4, %5, %6, %7, "                                    \
        " %8, %9, %10, %11, %12, %13, %14, %15, "                              \
        " %16, %17, %18, %19, %20, %21, %22, %23, "                            \
        " %24, %25, %26, %27, %28, %29, %30, %31}, [%32];"                     \
        : "=r"((r)[0]),  "=r"((r)[1]),  "=r"((r)[2]),  "=r"((r)[3]),           \
          "=r"((r)[4]),  "=r"((r)[5]),  "=r"((r)[6]),  "=r"((r)[7]),           \
          "=r"((r)[8]),  "=r"((r)[9]),  "=r"((r)[10]), "=r"((r)[11]),          \
          "=r"((r)[12]), "=r"((r)[13]), "=r"((r)[14]), "=r"((r)[15]),          \
          "=r"((r)[16]), "=r"((r)[17]), "=r"((r)[18]), "=r"((r)[19]),          \
          "=r"((r)[20]), "=r"((r)[21]), "=r"((r)[22]), "=r"((r)[23]),          \
          "=r"((r)[24]), "=r"((r)[25]), "=r"((r)[26]), "=r"((r)[27]),          \
          "=r"((r)[28]), "=r"((r)[29]), "=r"((r)[30]), "=r"((r)[31])           \
        : "r"(addr))
#define TMEM_WAIT_LD() asm volatile("tcgen05.wait::ld.sync.aligned;" ::: "memory")
#endif  // HAS_TCGEN05

// ---------------- prep kernels ----------------
__global__ void prep_A_kernel(const float* __restrict__ x) {
    size_t i = ((size_t)blockIdx.x * blockDim.x + threadIdx.x) * 4;
    if (i >= (size_t)TOKENS * KIN) return;
    float4 v = *reinterpret_cast<const float4*>(x + i);
    float vv[4] = {v.x, v.y, v.z, v.w};
    unsigned short h[4];
#pragma unroll
    for (int j = 0; j < 4; j++)
        h[j] = __half_as_ushort(__float2half_rn(vv[j]));
    *reinterpret_cast<ushort4*>(reinterpret_cast<unsigned short*>(g_Ah) + i) =
        make_ushort4(h[0], h[1], h[2], h[3]);
}

__global__ void prep_B_kernel(const float* __restrict__ w) {
    size_t i = ((size_t)blockIdx.x * blockDim.x + threadIdx.x) * 4;
    if (i >= (size_t)NOUT * KIN) return;
    float4 v = *reinterpret_cast<const float4*>(w + i);
    float vv[4] = {v.x, v.y, v.z, v.w};
    unsigned short s[4];
#pragma unroll
    for (int j = 0; j < 4; j++) {
        float sv = (vv[j] > 0.0f) ? 1.0f : ((vv[j] < 0.0f) ? -1.0f : 0.0f);
        s[j] = __half_as_ushort(__float2half_rn(sv));
    }
    *reinterpret_cast<ushort4*>(reinterpret_cast<unsigned short*>(g_Bs) + i) =
        make_ushort4(s[0], s[1], s[2], s[3]);
}

// ---------------- main GEMM kernel ----------------
__global__ __launch_bounds__(256, 1)
void bingemm_kernel(const float* __restrict__ bias, float* __restrict__ out) {
    extern __shared__ char smem[];

#if HAS_TCGEN05
    // ==================== Path A: tcgen05 ====================
    const uint32_t sb = smem_u32(smem);
    const int tid = threadIdx.x;
    const int wid = tid >> 5;
    const int lid = tid & 31;
    const int ntile = blockIdx.x;   // 0..15
    const int mtile = blockIdx.y;   // 0..31

    if (wid == 0) tmem_alloc(sb + SM_PTR, 512);
    if (tid == 0) {
        mbar_init(sb + SM_MBAR + 0, 1);
        mbar_init(sb + SM_MBAR + 8, 1);
        mbar_init(sb + SM_MBAR + 16, 1);
    }
    __syncthreads();
    uint32_t tmem;
    asm volatile("ld.shared.b32 %0, [%1];" : "=r"(tmem) : "r"(sb + SM_PTR));
    if (wid == 0) tmem_relinquish();

    const __half* Ap = g_Ah + (size_t)mtile * BM * KIN;
    const __half* Bp = g_Bs + (size_t)ntile * BN * KIN;

    for (int kc = 0; kc < NKC; kc++) {
        const int st = kc % NSTAGE;
        const uint32_t stb = 1024u + (uint32_t)st * STAGE_SZ;
        if (kc >= NSTAGE)
            mbar_wait(sb + SM_MBAR + 8 * st, (uint32_t)((kc / NSTAGE - 1) & 1));

        const int koff = kc * BK;
        // A: 256 rows x 128B -> 2048 x 16B chunks (halves contiguous: +0 / +16384)
#pragma unroll 8
        for (int c = tid; c < 2048; c += 256) {
            int row = c >> 3, p = c & 7;
            uint4 v = *reinterpret_cast<const uint4*>(Ap + (size_t)row * KIN + koff + p * 8);
            uint32_t off = SWZ((uint32_t)((row << 7) | (p << 4)));
            *reinterpret_cast<uint4*>(smem + stb + off) = v;
        }
        // B: 256 rows x 128B
#pragma unroll 8
        for (int c = tid; c < 2048; c += 256) {
            int row = c >> 3, p = c & 7;
            uint4 v = *reinterpret_cast<const uint4*>(Bp + (size_t)row * KIN + koff + p * 8);
            uint32_t off = SWZ((uint32_t)((row << 7) | (p << 4)));
            *reinterpret_cast<uint4*>(smem + stb + 32768 + off) = v;
        }
        __syncthreads();

        if (wid == 0) {
            if (elect_one()) {
                fence_proxy_async_cta();
                uint64_t a0 = make_desc(sb + stb);
                uint64_t a1 = make_desc(sb + stb + 16384);
                uint64_t bd = make_desc(sb + stb + 32768);
#pragma unroll
                for (int s = 0; s < 4; s++) {
                    bool acc = (kc > 0) || (s > 0);
                    mma_f16_ss(tmem,       a0 + 2 * s, bd + 2 * s, MMA_IDESC, acc);
                    mma_f16_ss(tmem + 256, a1 + 2 * s, bd + 2 * s, MMA_IDESC, acc);
                }
                mma_commit(sb + SM_MBAR + 8 * st);
            }
        }
        // no wait: next iteration fills a different stage (overlap with MMA)
    }

    // drain: wait last commit of each stage
#pragma unroll
    for (int st = 0; st < NSTAGE; st++) {
        int cnt = (NKC - st + NSTAGE - 1) / NSTAGE;   // commits to this stage
        mbar_wait(sb + SM_MBAR + 8 * st, (uint32_t)((cnt - 1) & 1));
    }
    __syncthreads();
    tc_fence_after();

    // Epilogue: warp w -> m-half h=w>>2 (D cols h*256), subpartition s=w&3.
    // 8 col-chunks of 32; stage 256 rows x 32 floats (32KB), coalesced STG.
    const int sub  = wid & 3;
    const int half = wid >> 2;
    const int m    = half * 128 + sub * 32 + lid;   // 0..255
    float* stage = reinterpret_cast<float*>(smem + 1024);
    const size_t orow0 = (size_t)mtile * BM;
    const int    ncol0 = ntile * BN;
    const float  bv = __ldg(&bias[ncol0 + (tid & 31)]);  // col = it*32 + (tid&31)

    for (int it = 0; it < 8; it++) {
        uint32_t r[32];
        LDTM_X32(r, tmem + (uint32_t)(half * 256 + it * 32));
        TMEM_WAIT_LD();
#pragma unroll
        for (int c = 0; c < 32; c++)
            stage[m * 32 + (c ^ (m & 31))] = __uint_as_float(r[c]);
        __syncthreads();
        const float bvi = __ldg(&bias[ncol0 + it * 32 + (tid & 31)]);
#pragma unroll 8
        for (int e = tid; e < 256 * 32; e += 256) {
            int row = e >> 5;
            int c   = e & 31;
            float v = stage[row * 32 + (c ^ (row & 31))];
            out[(orow0 + row) * (size_t)NOUT + (ncol0 + it * 32 + c)] = v + bvi;
        }
        __syncthreads();
    }
    (void)bv;

    if (wid == 0) tmem_dealloc(tmem, 512);

#else
    // ============ Path B: SIMT fallback (compile-only on plain sm_103; ============
    // ============ never selected at runtime on sm_103a hardware)       ============
    const int tid = threadIdx.x;
    const int ntile = blockIdx.x;
    const int mtile = blockIdx.y;
    const int row = mtile * BM + tid;   // 256 threads -> 256 rows
    const __half* Arow = g_Ah + (size_t)row * KIN;
    for (int c = 0; c < BN; c++) {
        const __half* Brow = g_Bs + (size_t)(ntile * BN + c) * KIN;
        float acc = 0.0f;
        for (int k = 0; k < KIN; k += 2) {
            float2 a = __half22float2(*reinterpret_cast<const __half2*>(Arow + k));
            float2 b = __half22float2(*reinterpret_cast<const __half2*>(Brow + k));
            acc += a.x * b.x + a.y * b.y;
        }
        out[(size_t)row * NOUT + ntile * BN + c] = acc + bias[ntile * BN + c];
    }
    (void)smem;
#endif
}

// ---------------- launch ----------------
extern "C" void kernel_launch(void* const* d_in, const int* in_sizes, int n_in,
                              void* d_out, int out_size) {
    const float* x    = (const float*)d_in[0];
    const float* w    = (const float*)d_in[1];
    const float* bias = (const float*)d_in[2];
    float* out        = (float*)d_out;

    {
        size_t n4 = (size_t)TOKENS * KIN / 4;
        prep_A_kernel<<<(unsigned)((n4 + 255) / 256), 256>>>(x);
    }
    {
        size_t n4 = (size_t)NOUT * KIN / 4;
        prep_B_kernel<<<(unsigned)((n4 + 255) / 256), 256>>>(w);
    }

    cudaFuncSetAttribute(bingemm_kernel,
                         cudaFuncAttributeMaxDynamicSharedMemorySize, SMEM_BYTES);
    dim3 grid(NOUT / BN, TOKENS / BM);   // (16, 32)
    bingemm_kernel<<<grid, 256, SMEM_BYTES>>>(bias, out);
}

// round 4
// speedup vs baseline: 2.3399x; 1.4904x over previous
#include <cuda_runtime.h>
#include <cuda_fp16.h>
#include <cuda.h>
#include <cstdint>
#include <cstddef>

// ============================================================
// BinaryLinear: out[t,o] = sum_k x[t,k]*sign(w[o,k]) + bias[o]
// R4: fp16 single-term (rel_err ~2e-4), tcgen05 cg1 SS MMA,
// BM=256 (2 x M=128 dispatches) x BN=256, BK=64, 3-stage pipeline.
// Fills via TMA; cluster(1,2) with multicast B (halves B L2 traffic);
// multicast tcgen05.commit coordinates stage reuse across the pair.
// ============================================================

#if defined(__CUDA_ARCH_FEAT_SM103_ALL) || defined(__CUDA_ARCH_FEAT_SM100_ALL) || defined(__CUDA_ARCH_FEAT_SM101_ALL)
#define HAS_TCGEN05 1
#else
#define HAS_TCGEN05 0
#endif

static constexpr int TOKENS = 8192;
static constexpr int NOUT   = 4096;
static constexpr int KIN    = 4096;

static constexpr int BM = 256, BN = 256, BK = 64;
static constexpr int NKC = KIN / BK;   // 64
static constexpr int NSTAGE = 3;

// idesc kind::f16 (fp16 in, fp32 acc): dtype F32(bit4), atype=btype=F16(0)
static constexpr uint32_t MMA_IDESC =
    0x10u | (uint32_t)((BN / 8) << 17) | (uint32_t)((128 / 16) << 24);

// smem: header 1024B, 3 stages x 64KB.
// stage: A rows 0-127 @ +0, rows 128-255 @ +16384, B @ +32768 (two 16KB halves)
static constexpr int SM_PTR   = 0;
static constexpr int SM_FULL  = 8;    // full[s] = 8 + 8s
static constexpr int SM_FREE  = 32;   // free[s] = 32 + 8s
static constexpr int STAGE_SZ = 65536;
static constexpr int SMEM_BYTES = 1024 + NSTAGE * STAGE_SZ;   // 197632
static constexpr uint32_t STAGE_TX = 65536;  // A 32KB + B(full, via 2 mcast halves) 32KB

// Scratch (static device globals — no runtime allocation)
__device__ __align__(16) __half g_Ah[(size_t)TOKENS * KIN];   // 64 MB
__device__ __align__(16) __half g_Bs[(size_t)NOUT   * KIN];   // 32 MB

// ---------------- helpers ----------------
static __device__ __forceinline__ uint32_t smem_u32(const void* p) {
    uint32_t a;
    asm("{ .reg .u64 t; cvta.to.shared.u64 t, %1; cvt.u32.u64 %0, t; }"
        : "=r"(a) : "l"(p));
    return a;
}
static __device__ __forceinline__ uint32_t elect_one() {
    uint32_t r;
    asm volatile("{ .reg .pred p; elect.sync _|p, 0xFFFFFFFF; selp.b32 %0, 1, 0, p; }"
                 : "=r"(r));
    return r;
}
static __device__ __forceinline__ void mbar_init(uint32_t mbar, uint32_t count) {
    asm volatile("mbarrier.init.shared.b64 [%0], %1;" :: "r"(mbar), "r"(count) : "memory");
}
static __device__ __forceinline__ void mbar_wait(uint32_t mbar, uint32_t parity) {
    asm volatile(
        "{\n\t"
        ".reg .pred P;\n\t"
        "WL_%=:\n\t"
        "mbarrier.try_wait.parity.acquire.cta.shared::cta.b64 P, [%0], %1, 0x989680;\n\t"
        "@P bra WD_%=;\n\t"
        "bra WL_%=;\n\t"
        "WD_%=:\n\t"
        "}"
        :: "r"(mbar), "r"(parity) : "memory");
}
static __device__ __forceinline__ void mbar_expect_tx(uint32_t mbar, uint32_t bytes) {
    asm volatile("mbarrier.arrive.expect_tx.shared.b64 _, [%0], %1;"
                 :: "r"(mbar), "r"(bytes) : "memory");
}
static __device__ __forceinline__ uint32_t ctarank() {
    uint32_t r;
    asm("mov.u32 %0, %%cluster_ctarank;" : "=r"(r));
    return r;
}
#define CLUSTER_SYNC() do {                                         \
    asm volatile("barrier.cluster.arrive.aligned;" ::: "memory");   \
    asm volatile("barrier.cluster.wait.aligned;" ::: "memory");     \
} while (0)

#if HAS_TCGEN05
static __device__ __forceinline__ void tmem_alloc(uint32_t smem_dst, uint32_t ncols) {
    asm volatile("tcgen05.alloc.cta_group::1.sync.aligned.shared::cta.b32 [%0], %1;"
                 :: "r"(smem_dst), "r"(ncols) : "memory");
}
static __device__ __forceinline__ void tmem_relinquish() {
    asm volatile("tcgen05.relinquish_alloc_permit.cta_group::1.sync.aligned;");
}
static __device__ __forceinline__ void tmem_dealloc(uint32_t tmem, uint32_t ncols) {
    asm volatile("tcgen05.dealloc.cta_group::1.sync.aligned.b32 %0, %1;"
                 :: "r"(tmem), "r"(ncols));
}
static __device__ __forceinline__ void tc_fence_after() {
    asm volatile("tcgen05.fence::after_thread_sync;" ::: "memory");
}
static __device__ __forceinline__ void mma_commit_mcast(uint32_t mbar, uint16_t mask) {
    asm volatile(
        "tcgen05.commit.cta_group::1.mbarrier::arrive::one.shared::cluster.multicast::cluster.b64 [%0], %1;"
        :: "r"(mbar), "h"(mask) : "memory");
}
static __device__ __forceinline__ void mma_f16_ss(uint32_t d_tmem, uint64_t a_desc,
                                                  uint64_t b_desc, uint32_t idesc,
                                                  bool acc) {
    uint32_t en = acc ? 1u : 0u;
    asm volatile(
        "{\n\t"
        ".reg .pred p;\n\t"
        "setp.ne.u32 p, %5, 0;\n\t"
        "tcgen05.mma.cta_group::1.kind::f16 [%0], %1, %2, %3, {%4, %4, %4, %4}, p;\n\t"
        "}"
        :: "r"(d_tmem), "l"(a_desc), "l"(b_desc), "r"(idesc), "r"(0u), "r"(en)
        : "memory");
}
static __device__ __forceinline__ uint64_t make_desc(uint32_t smem_addr) {
    const uint64_t base =
        (uint64_t(2) << 61) | (uint64_t(1) << 46) | (uint64_t(64) << 32) | (uint64_t(1) << 16);
    return base | ((uint64_t)(smem_addr >> 4) & 0x3FFFu);
}
static __device__ __forceinline__ void tma_2d(uint32_t smem_dst, const void* map,
                                              int32_t x, int32_t y, uint32_t mbar) {
    asm volatile(
        "cp.async.bulk.tensor.2d.shared::cta.global.tile.mbarrier::complete_tx::bytes "
        "[%0], [%1, {%2, %3}], [%4];"
        :: "r"(smem_dst), "l"(map), "r"(x), "r"(y), "r"(mbar) : "memory");
}
static __device__ __forceinline__ void tma_2d_mcast(uint32_t smem_dst, const void* map,
                                                    int32_t x, int32_t y, uint32_t mbar,
                                                    uint16_t mask) {
    asm volatile(
        "cp.async.bulk.tensor.2d.shared::cluster.global.tile.mbarrier::complete_tx::bytes"
        ".multicast::cluster [%0], [%1, {%2, %3}], [%4], %5;"
        :: "r"(smem_dst), "l"(map), "r"(x), "r"(y), "r"(mbar), "h"(mask) : "memory");
}
#define LDTM_X32(r, addr)                                                      \
    asm volatile(                                                              \
        "tcgen05.ld.sync.aligned.32x32b.x32.b32 "                              \
        "{%0, %1, %2, %3, %4, %5, %6, %7, "                                    \
        " %8, %9, %10, %11, %12, %13, %14, %15, "                              \
        " %16, %17, %18, %19, %20, %21, %22, %23, "                            \
        " %24, %25, %26, %27, %28, %29, %30, %31}, [%32];"                     \
        : "=r"((r)[0]),  "=r"((r)[1]),  "=r"((r)[2]),  "=r"((r)[3]),           \
          "=r"((r)[4]),  "=r"((r)[5]),  "=r"((r)[6]),  "=r"((r)[7]),           \
          "=r"((r)[8]),  "=r"((r)[9]),  "=r"((r)[10]), "=r"((r)[11]),          \
          "=r"((r)[12]), "=r"((r)[13]), "=r"((r)[14]), "=r"((r)[15]),          \
          "=r"((r)[16]), "=r"((r)[17]), "=r"((r)[18]), "=r"((r)[19]),          \
          "=r"((r)[20]), "=r"((r)[21]), "=r"((r)[22]), "=r"((r)[23]),          \
          "=r"((r)[24]), "=r"((r)[25]), "=r"((r)[26]), "=r"((r)[27]),          \
          "=r"((r)[28]), "=r"((r)[29]), "=r"((r)[30]), "=r"((r)[31])           \
        : "r"(addr))
#define TMEM_WAIT_LD() asm volatile("tcgen05.wait::ld.sync.aligned;" ::: "memory")
#endif  // HAS_TCGEN05

// ---------------- prep kernels ----------------
__global__ void prep_A_kernel(const float* __restrict__ x) {
    size_t i = ((size_t)blockIdx.x * blockDim.x + threadIdx.x) * 4;
    if (i >= (size_t)TOKENS * KIN) return;
    float4 v = *reinterpret_cast<const float4*>(x + i);
    float vv[4] = {v.x, v.y, v.z, v.w};
    unsigned short h[4];
#pragma unroll
    for (int j = 0; j < 4; j++)
        h[j] = __half_as_ushort(__float2half_rn(vv[j]));
    *reinterpret_cast<ushort4*>(reinterpret_cast<unsigned short*>(g_Ah) + i) =
        make_ushort4(h[0], h[1], h[2], h[3]);
}

__global__ void prep_B_kernel(const float* __restrict__ w) {
    size_t i = ((size_t)blockIdx.x * blockDim.x + threadIdx.x) * 4;
    if (i >= (size_t)NOUT * KIN) return;
    float4 v = *reinterpret_cast<const float4*>(w + i);
    float vv[4] = {v.x, v.y, v.z, v.w};
    unsigned short s[4];
#pragma unroll
    for (int j = 0; j < 4; j++) {
        float sv = (vv[j] > 0.0f) ? 1.0f : ((vv[j] < 0.0f) ? -1.0f : 0.0f);
        s[j] = __half_as_ushort(__float2half_rn(sv));
    }
    *reinterpret_cast<ushort4*>(reinterpret_cast<unsigned short*>(g_Bs) + i) =
        make_ushort4(s[0], s[1], s[2], s[3]);
}

// ---------------- main GEMM kernel ----------------
__global__ __launch_bounds__(256, 1)
void bingemm_kernel(const __grid_constant__ CUtensorMap tma_a,
                    const __grid_constant__ CUtensorMap tma_b,
                    const float* __restrict__ bias, float* __restrict__ out) {
    extern __shared__ char smem[];

#if HAS_TCGEN05
    const uint32_t sb = smem_u32(smem);
    const int tid = threadIdx.x;
    const int wid = tid >> 5;
    const int lid = tid & 31;
    const int ntile = blockIdx.x;   // 0..15
    const int mtile = blockIdx.y;   // 0..31
    const uint32_t rank = ctarank();   // 0/1 within (1,2,1) cluster

    if (wid == 0) tmem_alloc(sb + SM_PTR, 512);
    if (tid == 0) {
#pragma unroll
        for (int s = 0; s < NSTAGE; s++) {
            mbar_init(sb + SM_FULL + 8 * s, 1);   // local expect_tx arrive
            mbar_init(sb + SM_FREE + 8 * s, 2);   // commit from both cluster CTAs
        }
    }
    __syncthreads();
    uint32_t tmem;
    asm volatile("ld.shared.b32 %0, [%1];" : "=r"(tmem) : "r"(sb + SM_PTR));
    if (wid == 0) tmem_relinquish();

    // all mbarriers visible cluster-wide before any multicast TMA
    CLUSTER_SYNC();

    const int arow0 = mtile * BM;                  // A rows
    const int brow0 = ntile * BN + (int)rank * 128;  // this CTA's B slice rows

    if (wid == 0 && elect_one()) {
        // ---- prologue: fill stages 0..2 ----
#pragma unroll
        for (int s = 0; s < NSTAGE; s++) {
            const uint32_t stb = sb + 1024u + (uint32_t)s * STAGE_SZ;
            mbar_expect_tx(sb + SM_FULL + 8 * s, STAGE_TX);
            tma_2d(stb, &tma_a, s * BK, arow0, sb + SM_FULL + 8 * s);
            tma_2d_mcast(stb + 32768 + rank * 16384, &tma_b, s * BK, brow0,
                         sb + SM_FULL + 8 * s, 3);
        }
        // ---- mainloop ----
        for (int kc = 0; kc < NKC; kc++) {
            const int st = kc % NSTAGE;
            const uint32_t ph = (uint32_t)((kc / NSTAGE) & 1);
            const uint32_t stb = sb + 1024u + (uint32_t)st * STAGE_SZ;
            mbar_wait(sb + SM_FULL + 8 * st, ph);
            uint64_t a0 = make_desc(stb);
            uint64_t a1 = make_desc(stb + 16384);
            uint64_t bd = make_desc(stb + 32768);
#pragma unroll
            for (int s = 0; s < 4; s++) {
                bool acc = (kc > 0) || (s > 0);
                mma_f16_ss(tmem,       a0 + 2 * s, bd + 2 * s, MMA_IDESC, acc);
                mma_f16_ss(tmem + 256, a1 + 2 * s, bd + 2 * s, MMA_IDESC, acc);
            }
            mma_commit_mcast(sb + SM_FREE + 8 * st, 3);
            if (kc + NSTAGE < NKC) {
                // stage reusable only after BOTH CTAs' MMA batch kc completed
                mbar_wait(sb + SM_FREE + 8 * st, ph);
                const int kn = kc + NSTAGE;
                mbar_expect_tx(sb + SM_FULL + 8 * st, STAGE_TX);
                tma_2d(stb, &tma_a, kn * BK, arow0, sb + SM_FULL + 8 * st);
                tma_2d_mcast(stb + 32768 + rank * 16384, &tma_b, kn * BK, brow0,
                             sb + SM_FULL + 8 * st, 3);
            }
        }
        // ---- drain last 3 MMA batches ----
        for (int kc = NKC - NSTAGE; kc < NKC; kc++)
            mbar_wait(sb + SM_FREE + 8 * (kc % NSTAGE), (uint32_t)((kc / NSTAGE) & 1));
    }

    __syncthreads();
    tc_fence_after();

    // ---- epilogue: warp w -> m-half h=w>>2, subpartition s=w&3 ----
    const int sub  = wid & 3;
    const int half = wid >> 2;
    const int m    = half * 128 + sub * 32 + lid;   // 0..255
    float* stage = reinterpret_cast<float*>(smem + 1024);
    const size_t orow0 = (size_t)mtile * BM;
    const int    ncol0 = ntile * BN;

    for (int it = 0; it < 8; it++) {
        uint32_t r[32];
        LDTM_X32(r, tmem + (uint32_t)(half * 256 + it * 32));
        TMEM_WAIT_LD();
#pragma unroll
        for (int c = 0; c < 32; c++)
            stage[m * 32 + (c ^ (m & 31))] = __uint_as_float(r[c]);
        __syncthreads();
        const float bvi = __ldg(&bias[ncol0 + it * 32 + (tid & 31)]);
#pragma unroll 8
        for (int e = tid; e < 256 * 32; e += 256) {
            int row = e >> 5;
            int c   = e & 31;
            float v = stage[row * 32 + (c ^ (row & 31))];
            out[(orow0 + row) * (size_t)NOUT + (ncol0 + it * 32 + c)] = v + bvi;
        }
        __syncthreads();
    }

    if (wid == 0) tmem_dealloc(tmem, 512);
    CLUSTER_SYNC();

#else
    // ---- Path B: SIMT fallback (compile-only on plain sm_103 pass) ----
    (void)tma_a; (void)tma_b;
    const int tid = threadIdx.x;
    const int ntile = blockIdx.x;
    const int mtile = blockIdx.y;
    const int row = mtile * BM + tid;
    const __half* Arow = g_Ah + (size_t)row * KIN;
    for (int c = 0; c < BN; c++) {
        const __half* Brow = g_Bs + (size_t)(ntile * BN + c) * KIN;
        float acc = 0.0f;
        for (int k = 0; k < KIN; k += 2) {
            float2 a = __half22float2(*reinterpret_cast<const __half2*>(Arow + k));
            float2 b = __half22float2(*reinterpret_cast<const __half2*>(Brow + k));
            acc += a.x * b.x + a.y * b.y;
        }
        out[(size_t)row * NOUT + ntile * BN + c] = acc + bias[ntile * BN + c];
    }
    (void)smem;
#endif
}

// ---------------- host: tensor-map encode via cudart entry point ----------------
typedef CUresult (*PFN_tmEncode)(CUtensorMap*, CUtensorMapDataType, cuuint32_t, void*,
                                 const cuuint64_t*, const cuuint64_t*, const cuuint32_t*,
                                 const cuuint32_t*, CUtensorMapInterleave, CUtensorMapSwizzle,
                                 CUtensorMapL2promotion, CUtensorMapFloatOOBfill);

static void encode_map(PFN_tmEncode enc, CUtensorMap* tm, void* base,
                       uint64_t dim0, uint64_t dim1, uint32_t box0, uint32_t box1) {
    cuuint64_t dims[2]    = {dim0, dim1};
    cuuint64_t strides[1] = {dim0 * sizeof(__half)};
    cuuint32_t box[2]     = {box0, box1};
    cuuint32_t es[2]      = {1, 1};
    enc(tm, CU_TENSOR_MAP_DATA_TYPE_FLOAT16, 2, base, dims, strides, box, es,
        CU_TENSOR_MAP_INTERLEAVE_NONE, CU_TENSOR_MAP_SWIZZLE_128B,
        CU_TENSOR_MAP_L2_PROMOTION_L2_128B, CU_TENSOR_MAP_FLOAT_OOB_FILL_NONE);
}

extern "C" void kernel_launch(void* const* d_in, const int* in_sizes, int n_in,
                              void* d_out, int out_size) {
    const float* x    = (const float*)d_in[0];
    const float* w    = (const float*)d_in[1];
    const float* bias = (const float*)d_in[2];
    float* out        = (float*)d_out;

    {
        size_t n4 = (size_t)TOKENS * KIN / 4;
        prep_A_kernel<<<(unsigned)((n4 + 255) / 256), 256>>>(x);
    }
    {
        size_t n4 = (size_t)NOUT * KIN / 4;
        prep_B_kernel<<<(unsigned)((n4 + 255) / 256), 256>>>(w);
    }

    // Build TMA descriptors (host-side CPU work; no CUDA stream ops, no allocs)
    void* encFn = nullptr;
    cudaDriverEntryPointQueryResult qr;
    cudaGetDriverEntryPoint("cuTensorMapEncodeTiled", &encFn, cudaEnableDefault, &qr);
    PFN_tmEncode enc = (PFN_tmEncode)encFn;

    void *pA = nullptr, *pB = nullptr;
    cudaGetSymbolAddress(&pA, g_Ah);
    cudaGetSymbolAddress(&pB, g_Bs);

    CUtensorMap tmA, tmB;
    encode_map(enc, &tmA, pA, KIN, TOKENS, BK, 256);   // A box: 64 elems x 256 rows
    encode_map(enc, &tmB, pB, KIN, NOUT,   BK, 128);   // B box: 64 elems x 128 rows

    cudaFuncSetAttribute(bingemm_kernel,
                         cudaFuncAttributeMaxDynamicSharedMemorySize, SMEM_BYTES);

    cudaLaunchConfig_t cfg = {};
    cfg.gridDim  = dim3(NOUT / BN, TOKENS / BM, 1);   // (16, 32)
    cfg.blockDim = dim3(256, 1, 1);
    cfg.dynamicSmemBytes = SMEM_BYTES;
    cudaLaunchAttribute attrs[1];
    attrs[0].id = cudaLaunchAttributeClusterDimension;
    attrs[0].val.clusterDim.x = 1;
    attrs[0].val.clusterDim.y = 2;
    attrs[0].val.clusterDim.z = 1;
    cfg.attrs = attrs;
    cfg.numAttrs = 1;
    cudaLaunchKernelEx(&cfg, bingemm_kernel, tmA, tmB, bias, out);
}

// round 5
// speedup vs baseline: 2.7501x; 1.1753x over previous
#include <cuda_runtime.h>
#include <cuda_fp16.h>
#include <cuda.h>
#include <cstdint>
#include <cstddef>

// ============================================================
// BinaryLinear: out[t,o] = sum_k x[t,k]*sign(w[o,k]) + bias[o]
// R5: warp-specialized producer/consumer.
//   warp 0 (elect): MMA issue + commit (never blocks on refill)
//   warp 1 (elect): TMA refill driven by free[st] (MMA completion)
// fp16 single-term, tcgen05 cg1 SS MMA, BM=256 x BN=256, BK=64,
// 3-stage pipeline, cluster(1,2) with multicast B.
// ============================================================

#if defined(__CUDA_ARCH_FEAT_SM103_ALL) || defined(__CUDA_ARCH_FEAT_SM100_ALL) || defined(__CUDA_ARCH_FEAT_SM101_ALL)
#define HAS_TCGEN05 1
#else
#define HAS_TCGEN05 0
#endif

static constexpr int TOKENS = 8192;
static constexpr int NOUT   = 4096;
static constexpr int KIN    = 4096;

static constexpr int BM = 256, BN = 256, BK = 64;
static constexpr int NKC = KIN / BK;   // 64
static constexpr int NSTAGE = 3;

// idesc kind::f16 (fp16 in, fp32 acc): dtype F32(bit4), atype=btype=F16(0)
static constexpr uint32_t MMA_IDESC =
    0x10u | (uint32_t)((BN / 8) << 17) | (uint32_t)((128 / 16) << 24);

// smem: header 1024B, 3 stages x 64KB.
// stage: A rows 0-127 @ +0, rows 128-255 @ +16384, B @ +32768 (two 16KB halves)
static constexpr int SM_PTR   = 0;
static constexpr int SM_FULL  = 8;    // full[s] = 8 + 8s
static constexpr int SM_FREE  = 32;   // free[s] = 32 + 8s
static constexpr int STAGE_SZ = 65536;
static constexpr int SMEM_BYTES = 1024 + NSTAGE * STAGE_SZ;   // 197632
static constexpr uint32_t STAGE_TX = 65536;  // A 32KB + B 32KB (2 mcast halves)

// Scratch (static device globals — no runtime allocation)
__device__ __align__(16) __half g_Ah[(size_t)TOKENS * KIN];   // 64 MB
__device__ __align__(16) __half g_Bs[(size_t)NOUT   * KIN];   // 32 MB

// ---------------- helpers ----------------
static __device__ __forceinline__ uint32_t smem_u32(const void* p) {
    uint32_t a;
    asm("{ .reg .u64 t; cvta.to.shared.u64 t, %1; cvt.u32.u64 %0, t; }"
        : "=r"(a) : "l"(p));
    return a;
}
static __device__ __forceinline__ uint32_t elect_one() {
    uint32_t r;
    asm volatile("{ .reg .pred p; elect.sync _|p, 0xFFFFFFFF; selp.b32 %0, 1, 0, p; }"
                 : "=r"(r));
    return r;
}
static __device__ __forceinline__ void mbar_init(uint32_t mbar, uint32_t count) {
    asm volatile("mbarrier.init.shared.b64 [%0], %1;" :: "r"(mbar), "r"(count) : "memory");
}
static __device__ __forceinline__ void mbar_wait(uint32_t mbar, uint32_t parity) {
    asm volatile(
        "{\n\t"
        ".reg .pred P;\n\t"
        "WL_%=:\n\t"
        "mbarrier.try_wait.parity.acquire.cta.shared::cta.b64 P, [%0], %1, 0x989680;\n\t"
        "@P bra WD_%=;\n\t"
        "bra WL_%=;\n\t"
        "WD_%=:\n\t"
        "}"
        :: "r"(mbar), "r"(parity) : "memory");
}
static __device__ __forceinline__ void mbar_expect_tx(uint32_t mbar, uint32_t bytes) {
    asm volatile("mbarrier.arrive.expect_tx.shared.b64 _, [%0], %1;"
                 :: "r"(mbar), "r"(bytes) : "memory");
}
static __device__ __forceinline__ uint32_t ctarank() {
    uint32_t r;
    asm("mov.u32 %0, %%cluster_ctarank;" : "=r"(r));
    return r;
}
#define CLUSTER_SYNC() do {                                         \
    asm volatile("barrier.cluster.arrive.aligned;" ::: "memory");   \
    asm volatile("barrier.cluster.wait.aligned;" ::: "memory");     \
} while (0)

#if HAS_TCGEN05
static __device__ __forceinline__ void tmem_alloc(uint32_t smem_dst, uint32_t ncols) {
    asm volatile("tcgen05.alloc.cta_group::1.sync.aligned.shared::cta.b32 [%0], %1;"
                 :: "r"(smem_dst), "r"(ncols) : "memory");
}
static __device__ __forceinline__ void tmem_relinquish() {
    asm volatile("tcgen05.relinquish_alloc_permit.cta_group::1.sync.aligned;");
}
static __device__ __forceinline__ void tmem_dealloc(uint32_t tmem, uint32_t ncols) {
    asm volatile("tcgen05.dealloc.cta_group::1.sync.aligned.b32 %0, %1;"
                 :: "r"(tmem), "r"(ncols));
}
static __device__ __forceinline__ void tc_fence_after() {
    asm volatile("tcgen05.fence::after_thread_sync;" ::: "memory");
}
static __device__ __forceinline__ void mma_commit_mcast(uint32_t mbar, uint16_t mask) {
    asm volatile(
        "tcgen05.commit.cta_group::1.mbarrier::arrive::one.shared::cluster.multicast::cluster.b64 [%0], %1;"
        :: "r"(mbar), "h"(mask) : "memory");
}
static __device__ __forceinline__ void mma_f16_ss(uint32_t d_tmem, uint64_t a_desc,
                                                  uint64_t b_desc, uint32_t idesc,
                                                  bool acc) {
    uint32_t en = acc ? 1u : 0u;
    asm volatile(
        "{\n\t"
        ".reg .pred p;\n\t"
        "setp.ne.u32 p, %5, 0;\n\t"
        "tcgen05.mma.cta_group::1.kind::f16 [%0], %1, %2, %3, {%4, %4, %4, %4}, p;\n\t"
        "}"
        :: "r"(d_tmem), "l"(a_desc), "l"(b_desc), "r"(idesc), "r"(0u), "r"(en)
        : "memory");
}
static __device__ __forceinline__ uint64_t make_desc(uint32_t smem_addr) {
    const uint64_t base =
        (uint64_t(2) << 61) | (uint64_t(1) << 46) | (uint64_t(64) << 32) | (uint64_t(1) << 16);
    return base | ((uint64_t)(smem_addr >> 4) & 0x3FFFu);
}
static __device__ __forceinline__ void tma_2d(uint32_t smem_dst, const void* map,
                                              int32_t x, int32_t y, uint32_t mbar) {
    asm volatile(
        "cp.async.bulk.tensor.2d.shared::cta.global.tile.mbarrier::complete_tx::bytes "
        "[%0], [%1, {%2, %3}], [%4];"
        :: "r"(smem_dst), "l"(map), "r"(x), "r"(y), "r"(mbar) : "memory");
}
static __device__ __forceinline__ void tma_2d_mcast(uint32_t smem_dst, const void* map,
                                                    int32_t x, int32_t y, uint32_t mbar,
                                                    uint16_t mask) {
    asm volatile(
        "cp.async.bulk.tensor.2d.shared::cluster.global.tile.mbarrier::complete_tx::bytes"
        ".multicast::cluster [%0], [%1, {%2, %3}], [%4], %5;"
        :: "r"(smem_dst), "l"(map), "r"(x), "r"(y), "r"(mbar), "h"(mask) : "memory");
}
#define LDTM_X32(r, addr)                                                      \
    asm volatile(                                                              \
        "tcgen05.ld.sync.aligned.32x32b.x32.b32 "                              \
        "{%0, %1, %2, %3, %4, %5, %6, %7, "                                    \
        " %8, %9, %10, %11, %12, %13, %14, %15, "                              \
        " %16, %17, %18, %19, %20, %21, %22, %23, "                            \
        " %24, %25, %26, %27, %28, %29, %30, %31}, [%32];"                     \
        : "=r"((r)[0]),  "=r"((r)[1]),  "=r"((r)[2]),  "=r"((r)[3]),           \
          "=r"((r)[4]),  "=r"((r)[5]),  "=r"((r)[6]),  "=r"((r)[7]),           \
          "=r"((r)[8]),  "=r"((r)[9]),  "=r"((r)[10]), "=r"((r)[11]),          \
          "=r"((r)[12]), "=r"((r)[13]), "=r"((r)[14]), "=r"((r)[15]),          \
          "=r"((r)[16]), "=r"((r)[17]), "=r"((r)[18]), "=r"((r)[19]),          \
          "=r"((r)[20]), "=r"((r)[21]), "=r"((r)[22]), "=r"((r)[23]),          \
          "=r"((r)[24]), "=r"((r)[25]), "=r"((r)[26]), "=r"((r)[27]),          \
          "=r"((r)[28]), "=r"((r)[29]), "=r"((r)[30]), "=r"((r)[31])           \
        : "r"(addr))
#define TMEM_WAIT_LD() asm volatile("tcgen05.wait::ld.sync.aligned;" ::: "memory")
#endif  // HAS_TCGEN05

// ---------------- prep kernels ----------------
__global__ void prep_A_kernel(const float* __restrict__ x) {
    size_t i = ((size_t)blockIdx.x * blockDim.x + threadIdx.x) * 4;
    if (i >= (size_t)TOKENS * KIN) return;
    float4 v = *reinterpret_cast<const float4*>(x + i);
    float vv[4] = {v.x, v.y, v.z, v.w};
    unsigned short h[4];
#pragma unroll
    for (int j = 0; j < 4; j++)
        h[j] = __half_as_ushort(__float2half_rn(vv[j]));
    *reinterpret_cast<ushort4*>(reinterpret_cast<unsigned short*>(g_Ah) + i) =
        make_ushort4(h[0], h[1], h[2], h[3]);
}

__global__ void prep_B_kernel(const float* __restrict__ w) {
    size_t i = ((size_t)blockIdx.x * blockDim.x + threadIdx.x) * 4;
    if (i >= (size_t)NOUT * KIN) return;
    float4 v = *reinterpret_cast<const float4*>(w + i);
    float vv[4] = {v.x, v.y, v.z, v.w};
    unsigned short s[4];
#pragma unroll
    for (int j = 0; j < 4; j++) {
        float sv = (vv[j] > 0.0f) ? 1.0f : ((vv[j] < 0.0f) ? -1.0f : 0.0f);
        s[j] = __half_as_ushort(__float2half_rn(sv));
    }
    *reinterpret_cast<ushort4*>(reinterpret_cast<unsigned short*>(g_Bs) + i) =
        make_ushort4(s[0], s[1], s[2], s[3]);
}

// ---------------- main GEMM kernel ----------------
__global__ __launch_bounds__(256, 1)
void bingemm_kernel(const __grid_constant__ CUtensorMap tma_a,
                    const __grid_constant__ CUtensorMap tma_b,
                    const float* __restrict__ bias, float* __restrict__ out) {
    extern __shared__ char smem[];

#if HAS_TCGEN05
    const uint32_t sb = smem_u32(smem);
    const int tid = threadIdx.x;
    const int wid = tid >> 5;
    const int lid = tid & 31;
    const int ntile = blockIdx.x;   // 0..15
    const int mtile = blockIdx.y;   // 0..31
    const uint32_t rank = ctarank();   // 0/1 within (1,2,1) cluster

    if (wid == 0) tmem_alloc(sb + SM_PTR, 512);
    if (tid == 0) {
#pragma unroll
        for (int s = 0; s < NSTAGE; s++) {
            mbar_init(sb + SM_FULL + 8 * s, 1);   // expect_tx arrive (producer)
            mbar_init(sb + SM_FREE + 8 * s, 2);   // commit mcast from both CTAs
        }
    }
    __syncthreads();
    uint32_t tmem;
    asm volatile("ld.shared.b32 %0, [%1];" : "=r"(tmem) : "r"(sb + SM_PTR));
    if (wid == 0) tmem_relinquish();

    // all mbarriers visible cluster-wide before any multicast TMA
    CLUSTER_SYNC();

    const int arow0 = mtile * BM;                    // A rows
    const int brow0 = ntile * BN + (int)rank * 128;  // this CTA's B slice rows

    if (wid == 1 && elect_one()) {
        // ======== producer warp: TMA refills, gated by free[st] ========
        for (int f = 0; f < NKC; f++) {
            const int st = f % NSTAGE;
            const int r  = f / NSTAGE;
            // first round (r=0) passes immediately on fresh barrier (parity 1);
            // thereafter waits completion of MMA batch f-NSTAGE.
            mbar_wait(sb + SM_FREE + 8 * st, (uint32_t)((r + 1) & 1));
            const uint32_t stb = sb + 1024u + (uint32_t)st * STAGE_SZ;
            mbar_expect_tx(sb + SM_FULL + 8 * st, STAGE_TX);
            tma_2d(stb, &tma_a, f * BK, arow0, sb + SM_FULL + 8 * st);
            tma_2d_mcast(stb + 32768 + rank * 16384, &tma_b, f * BK, brow0,
                         sb + SM_FULL + 8 * st, 3);
        }
    } else if (wid == 0 && elect_one()) {
        // ======== consumer warp: MMA issue, never blocks on refill ========
        for (int kc = 0; kc < NKC; kc++) {
            const int st = kc % NSTAGE;
            const uint32_t ph = (uint32_t)((kc / NSTAGE) & 1);
            const uint32_t stb = sb + 1024u + (uint32_t)st * STAGE_SZ;
            mbar_wait(sb + SM_FULL + 8 * st, ph);
            uint64_t a0 = make_desc(stb);
            uint64_t a1 = make_desc(stb + 16384);
            uint64_t bd = make_desc(stb + 32768);
#pragma unroll
            for (int s = 0; s < 4; s++) {
                bool acc = (kc > 0) || (s > 0);
                mma_f16_ss(tmem,       a0 + 2 * s, bd + 2 * s, MMA_IDESC, acc);
                mma_f16_ss(tmem + 256, a1 + 2 * s, bd + 2 * s, MMA_IDESC, acc);
            }
            mma_commit_mcast(sb + SM_FREE + 8 * st, 3);
        }
        // drain: wait completion of the last NSTAGE batches
        for (int kc = NKC - NSTAGE; kc < NKC; kc++)
            mbar_wait(sb + SM_FREE + 8 * (kc % NSTAGE), (uint32_t)((kc / NSTAGE) & 1));
    }

    __syncthreads();
    tc_fence_after();

    // ---- epilogue: warp w -> m-half h=w>>2, subpartition s=w&3 ----
    const int sub  = wid & 3;
    const int half = wid >> 2;
    const int m    = half * 128 + sub * 32 + lid;   // 0..255
    float* stage = reinterpret_cast<float*>(smem + 1024);
    const size_t orow0 = (size_t)mtile * BM;
    const int    ncol0 = ntile * BN;

    for (int it = 0; it < 8; it++) {
        uint32_t r[32];
        LDTM_X32(r, tmem + (uint32_t)(half * 256 + it * 32));
        TMEM_WAIT_LD();
#pragma unroll
        for (int c = 0; c < 32; c++)
            stage[m * 32 + (c ^ (m & 31))] = __uint_as_float(r[c]);
        __syncthreads();
        const float bvi = __ldg(&bias[ncol0 + it * 32 + (tid & 31)]);
#pragma unroll 8
        for (int e = tid; e < 256 * 32; e += 256) {
            int row = e >> 5;
            int c   = e & 31;
            float v = stage[row * 32 + (c ^ (row & 31))];
            out[(orow0 + row) * (size_t)NOUT + (ncol0 + it * 32 + c)] = v + bvi;
        }
        __syncthreads();
    }

    if (wid == 0) tmem_dealloc(tmem, 512);
    CLUSTER_SYNC();

#else
    // ---- Path B: SIMT fallback (compile-only on plain sm_103 pass) ----
    (void)tma_a; (void)tma_b;
    const int tid = threadIdx.x;
    const int ntile = blockIdx.x;
    const int mtile = blockIdx.y;
    const int row = mtile * BM + tid;
    const __half* Arow = g_Ah + (size_t)row * KIN;
    for (int c = 0; c < BN; c++) {
        const __half* Brow = g_Bs + (size_t)(ntile * BN + c) * KIN;
        float acc = 0.0f;
        for (int k = 0; k < KIN; k += 2) {
            float2 a = __half22float2(*reinterpret_cast<const __half2*>(Arow + k));
            float2 b = __half22float2(*reinterpret_cast<const __half2*>(Brow + k));
            acc += a.x * b.x + a.y * b.y;
        }
        out[(size_t)row * NOUT + ntile * BN + c] = acc + bias[ntile * BN + c];
    }
    (void)smem;
#endif
}

// ---------------- host: tensor-map encode via cudart entry point ----------------
typedef CUresult (*PFN_tmEncode)(CUtensorMap*, CUtensorMapDataType, cuuint32_t, void*,
                                 const cuuint64_t*, const cuuint64_t*, const cuuint32_t*,
                                 const cuuint32_t*, CUtensorMapInterleave, CUtensorMapSwizzle,
                                 CUtensorMapL2promotion, CUtensorMapFloatOOBfill);

static void encode_map(PFN_tmEncode enc, CUtensorMap* tm, void* base,
                       uint64_t dim0, uint64_t dim1, uint32_t box0, uint32_t box1) {
    cuuint64_t dims[2]    = {dim0, dim1};
    cuuint64_t strides[1] = {dim0 * sizeof(__half)};
    cuuint32_t box[2]     = {box0, box1};
    cuuint32_t es[2]      = {1, 1};
    enc(tm, CU_TENSOR_MAP_DATA_TYPE_FLOAT16, 2, base, dims, strides, box, es,
        CU_TENSOR_MAP_INTERLEAVE_NONE, CU_TENSOR_MAP_SWIZZLE_128B,
        CU_TENSOR_MAP_L2_PROMOTION_L2_128B, CU_TENSOR_MAP_FLOAT_OOB_FILL_NONE);
}

extern "C" void kernel_launch(void* const* d_in, const int* in_sizes, int n_in,
                              void* d_out, int out_size) {
    const float* x    = (const float*)d_in[0];
    const float* w    = (const float*)d_in[1];
    const float* bias = (const float*)d_in[2];
    float* out        = (float*)d_out;

    {
        size_t n4 = (size_t)TOKENS * KIN / 4;
        prep_A_kernel<<<(unsigned)((n4 + 255) / 256), 256>>>(x);
    }
    {
        size_t n4 = (size_t)NOUT * KIN / 4;
        prep_B_kernel<<<(unsigned)((n4 + 255) / 256), 256>>>(w);
    }

    // Build TMA descriptors (host-side CPU work; no stream ops, no allocs)
    void* encFn = nullptr;
    cudaDriverEntryPointQueryResult qr;
    cudaGetDriverEntryPoint("cuTensorMapEncodeTiled", &encFn, cudaEnableDefault, &qr);
    PFN_tmEncode enc = (PFN_tmEncode)encFn;

    void *pA = nullptr, *pB = nullptr;
    cudaGetSymbolAddress(&pA, g_Ah);
    cudaGetSymbolAddress(&pB, g_Bs);

    CUtensorMap tmA, tmB;
    encode_map(enc, &tmA, pA, KIN, TOKENS, BK, 256);   // A box: 64 elems x 256 rows
    encode_map(enc, &tmB, pB, KIN, NOUT,   BK, 128);   // B box: 64 elems x 128 rows

    cudaFuncSetAttribute(bingemm_kernel,
                         cudaFuncAttributeMaxDynamicSharedMemorySize, SMEM_BYTES);

    cudaLaunchConfig_t cfg = {};
    cfg.gridDim  = dim3(NOUT / BN, TOKENS / BM, 1);   // (16, 32)
    cfg.blockDim = dim3(256, 1, 1);
    cfg.dynamicSmemBytes = SMEM_BYTES;
    cudaLaunchAttribute attrs[1];
    attrs[0].id = cudaLaunchAttributeClusterDimension;
    attrs[0].val.clusterDim.x = 1;
    attrs[0].val.clusterDim.y = 2;
    attrs[0].val.clusterDim.z = 1;
    cfg.attrs = attrs;
    cfg.numAttrs = 1;
    cudaLaunchKernelEx(&cfg, bingemm_kernel, tmA, tmB, bias, out);
}

// round 6
// speedup vs baseline: 2.8172x; 1.0244x over previous
#include <cuda_runtime.h>
#include <cuda_fp16.h>
#include <cuda.h>
#include <cstdint>
#include <cstddef>

// ============================================================
// BinaryLinear: out[t,o] = sum_k x[t,k]*sign(w[o,k]) + bias[o]
// R6: cluster (2,2) — A multicast across x-partners (same mtile),
// B multicast across y-partners (same ntile): L2 reads 1.6->1.07 GB.
// Warp-specialized producer/consumer; TMA-store async epilogue.
// fp16 single-term, tcgen05 cg1 SS MMA, BM=256 x BN=256, BK=64, 3 stages.
// ============================================================

#if defined(__CUDA_ARCH_FEAT_SM103_ALL) || defined(__CUDA_ARCH_FEAT_SM100_ALL) || defined(__CUDA_ARCH_FEAT_SM101_ALL)
#define HAS_TCGEN05 1
#else
#define HAS_TCGEN05 0
#endif

static constexpr int TOKENS = 8192;
static constexpr int NOUT   = 4096;
static constexpr int KIN    = 4096;

static constexpr int BM = 256, BN = 256, BK = 64;
static constexpr int NKC = KIN / BK;   // 64
static constexpr int NSTAGE = 3;

// idesc kind::f16 (fp16 in, fp32 acc): dtype F32(bit4), atype=btype=F16(0)
static constexpr uint32_t MMA_IDESC =
    0x10u | (uint32_t)((BN / 8) << 17) | (uint32_t)((128 / 16) << 24);

// smem: header 1024B, 3 stages x 64KB.
// stage: A rows 0-127 @ +0, rows 128-255 @ +16384, B @ +32768 (2 x 16KB halves)
static constexpr int SM_PTR   = 0;
static constexpr int SM_FULL  = 8;    // full[s] = 8 + 8s
static constexpr int SM_FREE  = 32;   // free[s] = 32 + 8s
static constexpr int STAGE_SZ = 65536;
static constexpr int SMEM_BYTES = 1024 + NSTAGE * STAGE_SZ;   // 197632
static constexpr uint32_t STAGE_TX = 65536;  // A 2x16KB + B 2x16KB (multicast)

// Scratch (static device globals — no runtime allocation)
__device__ __align__(16) __half g_Ah[(size_t)TOKENS * KIN];   // 64 MB
__device__ __align__(16) __half g_Bs[(size_t)NOUT   * KIN];   // 32 MB

#define SWZ(o) ((o) ^ (((o) >> 3) & 0x70u))

// ---------------- helpers ----------------
static __device__ __forceinline__ uint32_t smem_u32(const void* p) {
    uint32_t a;
    asm("{ .reg .u64 t; cvta.to.shared.u64 t, %1; cvt.u32.u64 %0, t; }"
        : "=r"(a) : "l"(p));
    return a;
}
static __device__ __forceinline__ uint32_t elect_one() {
    uint32_t r;
    asm volatile("{ .reg .pred p; elect.sync _|p, 0xFFFFFFFF; selp.b32 %0, 1, 0, p; }"
                 : "=r"(r));
    return r;
}
static __device__ __forceinline__ void mbar_init(uint32_t mbar, uint32_t count) {
    asm volatile("mbarrier.init.shared.b64 [%0], %1;" :: "r"(mbar), "r"(count) : "memory");
}
static __device__ __forceinline__ void mbar_wait(uint32_t mbar, uint32_t parity) {
    asm volatile(
        "{\n\t"
        ".reg .pred P;\n\t"
        "WL_%=:\n\t"
        "mbarrier.try_wait.parity.acquire.cta.shared::cta.b64 P, [%0], %1, 0x989680;\n\t"
        "@P bra WD_%=;\n\t"
        "bra WL_%=;\n\t"
        "WD_%=:\n\t"
        "}"
        :: "r"(mbar), "r"(parity) : "memory");
}
static __device__ __forceinline__ void mbar_expect_tx(uint32_t mbar, uint32_t bytes) {
    asm volatile("mbarrier.arrive.expect_tx.shared.b64 _, [%0], %1;"
                 :: "r"(mbar), "r"(bytes) : "memory");
}
#define CLUSTER_SYNC() do {                                         \
    asm volatile("barrier.cluster.arrive.aligned;" ::: "memory");   \
    asm volatile("barrier.cluster.wait.aligned;" ::: "memory");     \
} while (0)

#if HAS_TCGEN05
static __device__ __forceinline__ void tmem_alloc(uint32_t smem_dst, uint32_t ncols) {
    asm volatile("tcgen05.alloc.cta_group::1.sync.aligned.shared::cta.b32 [%0], %1;"
                 :: "r"(smem_dst), "r"(ncols) : "memory");
}
static __device__ __forceinline__ void tmem_relinquish() {
    asm volatile("tcgen05.relinquish_alloc_permit.cta_group::1.sync.aligned;");
}
static __device__ __forceinline__ void tmem_dealloc(uint32_t tmem, uint32_t ncols) {
    asm volatile("tcgen05.dealloc.cta_group::1.sync.aligned.b32 %0, %1;"
                 :: "r"(tmem), "r"(ncols));
}
static __device__ __forceinline__ void tc_fence_after() {
    asm volatile("tcgen05.fence::after_thread_sync;" ::: "memory");
}
static __device__ __forceinline__ void fence_proxy_async_cta() {
    asm volatile("fence.proxy.async.shared::cta;" ::: "memory");
}
static __device__ __forceinline__ void mma_commit_mcast(uint32_t mbar, uint16_t mask) {
    asm volatile(
        "tcgen05.commit.cta_group::1.mbarrier::arrive::one.shared::cluster.multicast::cluster.b64 [%0], %1;"
        :: "r"(mbar), "h"(mask) : "memory");
}
static __device__ __forceinline__ void mma_f16_ss(uint32_t d_tmem, uint64_t a_desc,
                                                  uint64_t b_desc, uint32_t idesc,
                                                  bool acc) {
    uint32_t en = acc ? 1u : 0u;
    asm volatile(
        "{\n\t"
        ".reg .pred p;\n\t"
        "setp.ne.u32 p, %5, 0;\n\t"
        "tcgen05.mma.cta_group::1.kind::f16 [%0], %1, %2, %3, {%4, %4, %4, %4}, p;\n\t"
        "}"
        :: "r"(d_tmem), "l"(a_desc), "l"(b_desc), "r"(idesc), "r"(0u), "r"(en)
        : "memory");
}
static __device__ __forceinline__ uint64_t make_desc(uint32_t smem_addr) {
    const uint64_t base =
        (uint64_t(2) << 61) | (uint64_t(1) << 46) | (uint64_t(64) << 32) | (uint64_t(1) << 16);
    return base | ((uint64_t)(smem_addr >> 4) & 0x3FFFu);
}
static __device__ __forceinline__ void tma_2d_mcast(uint32_t smem_dst, const void* map,
                                                    int32_t x, int32_t y, uint32_t mbar,
                                                    uint16_t mask) {
    asm volatile(
        "cp.async.bulk.tensor.2d.shared::cluster.global.tile.mbarrier::complete_tx::bytes"
        ".multicast::cluster [%0], [%1, {%2, %3}], [%4], %5;"
        :: "r"(smem_dst), "l"(map), "r"(x), "r"(y), "r"(mbar), "h"(mask) : "memory");
}
static __device__ __forceinline__ void tma_store_2d(const void* map, int32_t x, int32_t y,
                                                    uint32_t smem_src) {
    asm volatile(
        "cp.async.bulk.tensor.2d.global.shared::cta.tile.bulk_group [%0, {%1, %2}], [%3];"
        :: "l"(map), "r"(x), "r"(y), "r"(smem_src) : "memory");
}
#define TMA_STORE_COMMIT() asm volatile("cp.async.bulk.commit_group;" ::: "memory")
#define TMA_STORE_WAIT(n)  asm volatile("cp.async.bulk.wait_group %0;" :: "n"(n) : "memory")
#define LDTM_X32(r, addr)                                                      \
    asm volatile(                                                              \
        "tcgen05.ld.sync.aligned.32x32b.x32.b32 "                              \
        "{%0, %1, %2, %3, %4, %5, %6, %7, "                                    \
        " %8, %9, %10, %11, %12, %13, %14, %15, "                              \
        " %16, %17, %18, %19, %20, %21, %22, %23, "                            \
        " %24, %25, %26, %27, %28, %29, %30, %31}, [%32];"                     \
        : "=r"((r)[0]),  "=r"((r)[1]),  "=r"((r)[2]),  "=r"((r)[3]),           \
          "=r"((r)[4]),  "=r"((r)[5]),  "=r"((r)[6]),  "=r"((r)[7]),           \
          "=r"((r)[8]),  "=r"((r)[9]),  "=r"((r)[10]), "=r"((r)[11]),          \
          "=r"((r)[12]), "=r"((r)[13]), "=r"((r)[14]), "=r"((r)[15]),          \
          "=r"((r)[16]), "=r"((r)[17]), "=r"((r)[18]), "=r"((r)[19]),          \
          "=r"((r)[20]), "=r"((r)[21]), "=r"((r)[22]), "=r"((r)[23]),          \
          "=r"((r)[24]), "=r"((r)[25]), "=r"((r)[26]), "=r"((r)[27]),          \
          "=r"((r)[28]), "=r"((r)[29]), "=r"((r)[30]), "=r"((r)[31])           \
        : "r"(addr))
#define TMEM_WAIT_LD() asm volatile("tcgen05.wait::ld.sync.aligned;" ::: "memory")
#endif  // HAS_TCGEN05

// ---------------- prep kernels ----------------
__global__ void prep_A_kernel(const float* __restrict__ x) {
    size_t i = ((size_t)blockIdx.x * blockDim.x + threadIdx.x) * 4;
    if (i >= (size_t)TOKENS * KIN) return;
    float4 v = *reinterpret_cast<const float4*>(x + i);
    float vv[4] = {v.x, v.y, v.z, v.w};
    unsigned short h[4];
#pragma unroll
    for (int j = 0; j < 4; j++)
        h[j] = __half_as_ushort(__float2half_rn(vv[j]));
    *reinterpret_cast<ushort4*>(reinterpret_cast<unsigned short*>(g_Ah) + i) =
        make_ushort4(h[0], h[1], h[2], h[3]);
}

__global__ void prep_B_kernel(const float* __restrict__ w) {
    size_t i = ((size_t)blockIdx.x * blockDim.x + threadIdx.x) * 4;
    if (i >= (size_t)NOUT * KIN) return;
    float4 v = *reinterpret_cast<const float4*>(w + i);
    float vv[4] = {v.x, v.y, v.z, v.w};
    unsigned short s[4];
#pragma unroll
    for (int j = 0; j < 4; j++) {
        float sv = (vv[j] > 0.0f) ? 1.0f : ((vv[j] < 0.0f) ? -1.0f : 0.0f);
        s[j] = __half_as_ushort(__float2half_rn(sv));
    }
    *reinterpret_cast<ushort4*>(reinterpret_cast<unsigned short*>(g_Bs) + i) =
        make_ushort4(s[0], s[1], s[2], s[3]);
}

// ---------------- main GEMM kernel ----------------
__global__ __launch_bounds__(256, 1)
void bingemm_kernel(const __grid_constant__ CUtensorMap tma_a,
                    const __grid_constant__ CUtensorMap tma_b,
                    const __grid_constant__ CUtensorMap tma_o,
                    const float* __restrict__ bias, float* __restrict__ out) {
    extern __shared__ char smem[];

#if HAS_TCGEN05
    const uint32_t sb = smem_u32(smem);
    const int tid = threadIdx.x;
    const int wid = tid >> 5;
    const int lid = tid & 31;
    const int ntile = blockIdx.x;   // 0..15
    const int mtile = blockIdx.y;   // 0..31

    // cluster (2,2): rank = rx + 2*ry (x-major HW linearization)
    const int rx = (int)(blockIdx.x & 1);
    const int ry = (int)(blockIdx.y & 1);
    const int rank = rx + 2 * ry;
    const uint16_t mask_A  = (uint16_t)(0x3u << (2 * ry));   // x-partners (share A)
    const uint16_t mask_B  = (uint16_t)(0x5u << rx);         // y-partners (share B)
    const uint16_t mask_CM = (uint16_t)((1u << rank) | (1u << (rank ^ 1)) | (1u << (rank ^ 2)));

    if (wid == 0) tmem_alloc(sb + SM_PTR, 512);
    if (tid == 0) {
#pragma unroll
        for (int s = 0; s < NSTAGE; s++) {
            mbar_init(sb + SM_FULL + 8 * s, 1);   // expect_tx arrive (self)
            mbar_init(sb + SM_FREE + 8 * s, 3);   // commits: self + x-partner + y-partner
        }
    }
    __syncthreads();
    uint32_t tmem;
    asm volatile("ld.shared.b32 %0, [%1];" : "=r"(tmem) : "r"(sb + SM_PTR));
    if (wid == 0) tmem_relinquish();

    // all mbarriers visible cluster-wide before any multicast TMA
    CLUSTER_SYNC();

    const int arow = mtile * BM + rx * 128;   // my A half (rows), mcast to x-pair
    const int brow = ntile * BN + ry * 128;   // my B half (rows), mcast to y-pair

    if (wid == 1 && elect_one()) {
        // ======== producer: TMA refills, gated by free[st] (3 commits) ========
        for (int f = 0; f < NKC; f++) {
            const int st = f % NSTAGE;
            const int r  = f / NSTAGE;
            mbar_wait(sb + SM_FREE + 8 * st, (uint32_t)((r + 1) & 1));
            const uint32_t stb = sb + 1024u + (uint32_t)st * STAGE_SZ;
            mbar_expect_tx(sb + SM_FULL + 8 * st, STAGE_TX);
            tma_2d_mcast(stb + (uint32_t)rx * 16384u, &tma_a, f * BK, arow,
                         sb + SM_FULL + 8 * st, mask_A);
            tma_2d_mcast(stb + 32768u + (uint32_t)ry * 16384u, &tma_b, f * BK, brow,
                         sb + SM_FULL + 8 * st, mask_B);
        }
    } else if (wid == 0 && elect_one()) {
        // ======== consumer: MMA issue, never blocks on refill ========
        for (int kc = 0; kc < NKC; kc++) {
            const int st = kc % NSTAGE;
            const uint32_t ph = (uint32_t)((kc / NSTAGE) & 1);
            const uint32_t stb = sb + 1024u + (uint32_t)st * STAGE_SZ;
            mbar_wait(sb + SM_FULL + 8 * st, ph);
            uint64_t a0 = make_desc(stb);
            uint64_t a1 = make_desc(stb + 16384);
            uint64_t bd = make_desc(stb + 32768);
#pragma unroll
            for (int s = 0; s < 4; s++) {
                bool acc = (kc > 0) || (s > 0);
                mma_f16_ss(tmem,       a0 + 2 * s, bd + 2 * s, MMA_IDESC, acc);
                mma_f16_ss(tmem + 256, a1 + 2 * s, bd + 2 * s, MMA_IDESC, acc);
            }
            mma_commit_mcast(sb + SM_FREE + 8 * st, mask_CM);
        }
        // drain: wait completion of the last NSTAGE batches (all 3 commits each)
        for (int kc = NKC - NSTAGE; kc < NKC; kc++)
            mbar_wait(sb + SM_FREE + 8 * (kc % NSTAGE), (uint32_t)((kc / NSTAGE) & 1));
    }

    __syncthreads();
    tc_fence_after();

    // ---- epilogue: LDTM -> +bias -> swizzled STS -> async TMA store ----
    // 4 rotating 32KB regions inside the (now idle) stage smem.
    const int sub  = wid & 3;
    const int half = wid >> 2;
    const int m    = half * 128 + sub * 32 + lid;   // 0..255 (tile row)
    const size_t orow0 = (size_t)mtile * BM;
    const int    ncol0 = ntile * BN;

    for (int it = 0; it < 8; it++) {
        if (wid == 0 && elect_one() && it >= 4) TMA_STORE_WAIT(3);
        __syncthreads();   // region (it&3) free for all threads

        uint32_t r[32];
        LDTM_X32(r, tmem + (uint32_t)(half * 256 + it * 32));
        TMEM_WAIT_LD();

        const float4* b4 = reinterpret_cast<const float4*>(bias + ncol0 + it * 32);
        const uint32_t reg = 1024u + (uint32_t)(it & 3) * 32768u;
#pragma unroll
        for (int j = 0; j < 8; j++) {
            float4 bb = __ldg(b4 + j);
            float4 v;
            v.x = __uint_as_float(r[4 * j + 0]) + bb.x;
            v.y = __uint_as_float(r[4 * j + 1]) + bb.y;
            v.z = __uint_as_float(r[4 * j + 2]) + bb.z;
            v.w = __uint_as_float(r[4 * j + 3]) + bb.w;
            uint32_t off = SWZ((uint32_t)(m * 128 + j * 16));
            *reinterpret_cast<float4*>(smem + reg + off) = v;
        }
        __syncthreads();
        if (wid == 0 && elect_one()) {
            fence_proxy_async_cta();
            tma_store_2d(&tma_o, ncol0 + it * 32, (int32_t)orow0, sb + reg);
            TMA_STORE_COMMIT();
        }
    }
    if (wid == 0 && elect_one()) TMA_STORE_WAIT(0);
    __syncthreads();

    if (wid == 0) tmem_dealloc(tmem, 512);
    CLUSTER_SYNC();
    (void)out;

#else
    // ---- Path B: SIMT fallback (compile-only on plain sm_103 pass) ----
    (void)tma_a; (void)tma_b; (void)tma_o;
    const int tid = threadIdx.x;
    const int ntile = blockIdx.x;
    const int mtile = blockIdx.y;
    const int row = mtile * BM + tid;
    const __half* Arow = g_Ah + (size_t)row * KIN;
    for (int c = 0; c < BN; c++) {
        const __half* Brow = g_Bs + (size_t)(ntile * BN + c) * KIN;
        float acc = 0.0f;
        for (int k = 0; k < KIN; k += 2) {
            float2 a = __half22float2(*reinterpret_cast<const __half2*>(Arow + k));
            float2 b = __half22float2(*reinterpret_cast<const __half2*>(Brow + k));
            acc += a.x * b.x + a.y * b.y;
        }
        out[(size_t)row * NOUT + ntile * BN + c] = acc + bias[ntile * BN + c];
    }
    (void)smem;
#endif
}

// ---------------- host: tensor-map encode via cudart entry point ----------------
typedef CUresult (*PFN_tmEncode)(CUtensorMap*, CUtensorMapDataType, cuuint32_t, void*,
                                 const cuuint64_t*, const cuuint64_t*, const cuuint32_t*,
                                 const cuuint32_t*, CUtensorMapInterleave, CUtensorMapSwizzle,
                                 CUtensorMapL2promotion, CUtensorMapFloatOOBfill);

static void encode_half_map(PFN_tmEncode enc, CUtensorMap* tm, void* base,
                            uint64_t dim0, uint64_t dim1, uint32_t box0, uint32_t box1) {
    cuuint64_t dims[2]    = {dim0, dim1};
    cuuint64_t strides[1] = {dim0 * sizeof(__half)};
    cuuint32_t box[2]     = {box0, box1};
    cuuint32_t es[2]      = {1, 1};
    enc(tm, CU_TENSOR_MAP_DATA_TYPE_FLOAT16, 2, base, dims, strides, box, es,
        CU_TENSOR_MAP_INTERLEAVE_NONE, CU_TENSOR_MAP_SWIZZLE_128B,
        CU_TENSOR_MAP_L2_PROMOTION_L2_128B, CU_TENSOR_MAP_FLOAT_OOB_FILL_NONE);
}

extern "C" void kernel_launch(void* const* d_in, const int* in_sizes, int n_in,
                              void* d_out, int out_size) {
    const float* x    = (const float*)d_in[0];
    const float* w    = (const float*)d_in[1];
    const float* bias = (const float*)d_in[2];
    float* out        = (float*)d_out;

    {
        size_t n4 = (size_t)TOKENS * KIN / 4;
        prep_A_kernel<<<(unsigned)((n4 + 255) / 256), 256>>>(x);
    }
    {
        size_t n4 = (size_t)NOUT * KIN / 4;
        prep_B_kernel<<<(unsigned)((n4 + 255) / 256), 256>>>(w);
    }

    // Build TMA descriptors (host-side CPU work; no stream ops, no allocs)
    void* encFn = nullptr;
    cudaDriverEntryPointQueryResult qr;
    cudaGetDriverEntryPoint("cuTensorMapEncodeTiled", &encFn, cudaEnableDefault, &qr);
    PFN_tmEncode enc = (PFN_tmEncode)encFn;

    void *pA = nullptr, *pB = nullptr;
    cudaGetSymbolAddress(&pA, g_Ah);
    cudaGetSymbolAddress(&pB, g_Bs);

    CUtensorMap tmA, tmB, tmO;
    encode_half_map(enc, &tmA, pA, KIN, TOKENS, BK, 128);  // A half-tile: 64 x 128
    encode_half_map(enc, &tmB, pB, KIN, NOUT,   BK, 128);  // B half-tile: 64 x 128
    {   // out map: fp32 [8192 x 4096], box 32 cols x 256 rows, SW128
        cuuint64_t dims[2]    = {NOUT, TOKENS};
        cuuint64_t strides[1] = {(cuuint64_t)NOUT * sizeof(float)};
        cuuint32_t box[2]     = {32, 256};
        cuuint32_t es[2]      = {1, 1};
        enc(&tmO, CU_TENSOR_MAP_DATA_TYPE_FLOAT32, 2, d_out, dims, strides, box, es,
            CU_TENSOR_MAP_INTERLEAVE_NONE, CU_TENSOR_MAP_SWIZZLE_128B,
            CU_TENSOR_MAP_L2_PROMOTION_L2_128B, CU_TENSOR_MAP_FLOAT_OOB_FILL_NONE);
    }

    cudaFuncSetAttribute(bingemm_kernel,
                         cudaFuncAttributeMaxDynamicSharedMemorySize, SMEM_BYTES);

    cudaLaunchConfig_t cfg = {};
    cfg.gridDim  = dim3(NOUT / BN, TOKENS / BM, 1);   // (16, 32)
    cfg.blockDim = dim3(256, 1, 1);
    cfg.dynamicSmemBytes = SMEM_BYTES;
    cudaLaunchAttribute attrs[1];
    attrs[0].id = cudaLaunchAttributeClusterDimension;
    attrs[0].val.clusterDim.x = 2;
    attrs[0].val.clusterDim.y = 2;
    attrs[0].val.clusterDim.z = 1;
    cfg.attrs = attrs;
    cfg.numAttrs = 1;
    cudaLaunchKernelEx(&cfg, bingemm_kernel, tmA, tmB, tmO, bias, out);
}